// round 6
// baseline (speedup 1.0000x reference)
#include <cuda_runtime.h>
#include <cstdint>

#define BATCH 4
#define EDIM 1024
#define CDIM 768
#define TLEN 1024
#define SLEN 1024
#define NH 16
#define DH 64
#define EPSV 1e-5f

// ---------------- scratch (static device globals; no allocation) ----------------
__device__ float g_wnq[EDIM * EDIM];
__device__ float g_wnkv[2 * EDIM * CDIM];               // [wnk ; wnv]
__device__ float g_wno[EDIM * EDIM];
__device__ float g_kvb[2 * EDIM];                       // [kb ; vb]
__device__ float g_xr[BATCH * EDIM * TLEN];             // tf32-rounded x
__device__ float g_cr[BATCH * CDIM * SLEN];             // tf32-rounded ctx
__device__ float g_q[BATCH * EDIM * TLEN];
__device__ float g_kv[(long)BATCH * 2 * EDIM * SLEN];   // [B][2E][S]
__device__ float g_p[(long)BATCH * NH * SLEN * TLEN];   // exp(scores) scratch
__device__ float g_r[BATCH * NH * SLEN];                // 1/rowsum (or 0)
__device__ float g_att[BATCH * EDIM * TLEN];            // att^T: [B][T][E]
__device__ unsigned char g_mask[BATCH * TLEN];
__device__ unsigned char g_mctx[BATCH * SLEN];

__device__ __forceinline__ float to_tf32(float x) {
    float r;
    asm("cvt.rna.tf32.f32 %0, %1;" : "=f"(r) : "f"(x));
    return r;
}
__device__ __forceinline__ uint32_t f2u(float x) { return __float_as_uint(x); }
__device__ __forceinline__ uint32_t smem_u32(const void* p) {
    uint32_t a;
    asm("{ .reg .u64 t; cvta.to.shared.u64 t, %1; cvt.u32.u64 %0, t; }" : "=r"(a) : "l"(p));
    return a;
}
#define CP16(dst, src) asm volatile("cp.async.cg.shared.global [%0], [%1], 16;" :: "r"(dst), "l"(src))
#define CPCOMMIT()     asm volatile("cp.async.commit_group;" ::: "memory")
#define CPWAIT(N)      asm volatile("cp.async.wait_group %0;" :: "n"(N) : "memory")

#define MMA_TF32(d, a, b) \
    asm volatile("mma.sync.aligned.m16n8k8.row.col.f32.tf32.tf32.f32 " \
                 "{%0,%1,%2,%3}, {%4,%5,%6,%7}, {%8,%9}, {%0,%1,%2,%3};" \
                 : "+f"((d)[0]), "+f"((d)[1]), "+f"((d)[2]), "+f"((d)[3]) \
                 : "r"((a)[0]), "r"((a)[1]), "r"((a)[2]), "r"((a)[3]), \
                   "r"((b)[0]), "r"((b)[1]))

// ================= mma.sync TF32 GEMM (cp.async 3-stage, conflict-free layouts) =======
// C[m,n] = sum_k A'[m,k] * B'[n,k]
//   A' from src [m,k] (TA=false, smem [m][k] str 36) or [k,m] (TA=true, smem [k][m] str 136)
//   B' from src [n,k] (TB=false, smem [n][k] str 36) or [k,n] (TB=true, smem [k][n] str 136)
// Operands must be pre-rounded to tf32 by producers.
// EPI 0: conv (bias + col-mask->0 + optional residual)
// EPI 2: plain + tf32-round on store
// EPI 3: exp-scores: c = mask[n] ? tf32(expf(c)) : 0
template <int EPI, bool TA, bool TB, int BN>
__global__ __launch_bounds__(256) void mma_gemm(
    const float* __restrict__ A0, int aDiv, long aStrZa, long aStrZb, int lda,
    const float* __restrict__ B0, int bDiv, long bStrZa, long bStrZb, int ldb,
    float* __restrict__ C0, int cDiv, long cStrZa, long cStrZb, int ldc,
    int K,
    const float* __restrict__ bias,
    const unsigned char* __restrict__ mask, int maskDiv, int maskLd,
    const float* __restrict__ res, long resStride)
{
    constexpr int BM = 128;
    constexpr int AFL = TA ? 32 * 136 : BM * 36;
    constexpr int BFL = TB ? 32 * 136 : BN * 36;
    constexpr int STG = AFL + BFL;
    constexpr int NS = 3;
    constexpr int WN = BN / 2;
    constexpr int NF = WN / 8;

    extern __shared__ float smf[];
    uint32_t sbase = smem_u32(smf);
    int tid = threadIdx.x, wid = tid >> 5, lane = tid & 31;
    int z = blockIdx.z;
    const float* A = A0 + (z / aDiv) * aStrZa + (z % aDiv) * aStrZb;
    const float* B = B0 + (z / bDiv) * bStrZa + (z % bDiv) * bStrZb;
    float* C = C0 + (z / cDiv) * cStrZa + (z % cDiv) * cStrZb;
    long mBase = (long)blockIdx.y * BM, nBase = (long)blockIdx.x * BN;

    float acc[2][NF][4];
#pragma unroll
    for (int i = 0; i < 2; ++i)
#pragma unroll
        for (int j = 0; j < NF; ++j)
#pragma unroll
            for (int t = 0; t < 4; ++t) acc[i][j][t] = 0.f;

    int nIter = K / 32;

    auto issue = [&](int stage, int k0) {
        uint32_t aoff = sbase + stage * STG * 4;
        if (TA) {
#pragma unroll
            for (int r = 0; r < 4; ++r) {
                int lin = tid + 256 * r;
                int k = lin >> 5, mq = (lin & 31) * 4;
                CP16(aoff + (k * 136 + mq) * 4, &A[(long)(k0 + k) * lda + mBase + mq]);
            }
        } else {
#pragma unroll
            for (int r = 0; r < BM / 32; ++r) {
                int lin = tid + 256 * r;
                int m = lin >> 3, kq = (lin & 7) * 4;
                CP16(aoff + (m * 36 + kq) * 4, &A[(mBase + m) * (long)lda + k0 + kq]);
            }
        }
        uint32_t boff = sbase + (stage * STG + AFL) * 4;
        if (TB) {
#pragma unroll
            for (int r = 0; r < 4; ++r) {
                int lin = tid + 256 * r;
                int k = lin >> 5, nq = (lin & 31) * 4;
                CP16(boff + (k * 136 + nq) * 4, &B[(long)(k0 + k) * ldb + nBase + nq]);
            }
        } else {
#pragma unroll
            for (int r = 0; r < BN / 32; ++r) {
                int lin = tid + 256 * r;
                int n = lin >> 3, kq = (lin & 7) * 4;
                CP16(boff + (n * 36 + kq) * 4, &B[(nBase + n) * (long)ldb + k0 + kq]);
            }
        }
    };

    int warpM = wid & 3, warpN = wid >> 2;
    int mW = warpM * 32, nW = warpN * WN;
    int c4 = lane & 3, r4 = lane >> 2;

    auto compute = [&](int stage) {
        const float* As = smf + stage * STG;
        const float* Bs = As + AFL;
#pragma unroll
        for (int kk = 0; kk < 32; kk += 8) {
            uint32_t a[2][4];
#pragma unroll
            for (int mf = 0; mf < 2; ++mf) {
                int m = mW + mf * 16 + r4;
                if (TA) {
                    a[mf][0] = f2u(As[(kk + c4) * 136 + m]);
                    a[mf][1] = f2u(As[(kk + c4) * 136 + m + 8]);
                    a[mf][2] = f2u(As[(kk + c4 + 4) * 136 + m]);
                    a[mf][3] = f2u(As[(kk + c4 + 4) * 136 + m + 8]);
                } else {
                    a[mf][0] = f2u(As[m * 36 + kk + c4]);
                    a[mf][1] = f2u(As[(m + 8) * 36 + kk + c4]);
                    a[mf][2] = f2u(As[m * 36 + kk + c4 + 4]);
                    a[mf][3] = f2u(As[(m + 8) * 36 + kk + c4 + 4]);
                }
            }
            uint32_t b[NF][2];
#pragma unroll
            for (int nf = 0; nf < NF; ++nf) {
                int n = nW + nf * 8 + r4;
                if (TB) {
                    b[nf][0] = f2u(Bs[(kk + c4) * 136 + n]);
                    b[nf][1] = f2u(Bs[(kk + c4 + 4) * 136 + n]);
                } else {
                    b[nf][0] = f2u(Bs[n * 36 + kk + c4]);
                    b[nf][1] = f2u(Bs[n * 36 + kk + c4 + 4]);
                }
            }
#pragma unroll
            for (int mf = 0; mf < 2; ++mf)
#pragma unroll
                for (int nf = 0; nf < NF; ++nf)
                    MMA_TF32(acc[mf][nf], a[mf], b[nf]);
        }
    };

    for (int s = 0; s < NS - 1; ++s) {
        if (s < nIter) issue(s, s * 32);
        CPCOMMIT();
    }
    for (int it = 0; it < nIter; ++it) {
        CPWAIT(NS - 2);
        __syncthreads();
        compute(it % NS);
        __syncthreads();
        int nx = it + NS - 1;
        if (nx < nIter) issue(nx % NS, nx * 32);
        CPCOMMIT();
    }

    // ---- epilogue ----
    int mb = z / maskDiv;
#pragma unroll
    for (int mf = 0; mf < 2; ++mf) {
#pragma unroll
        for (int half = 0; half < 2; ++half) {
            long m = mBase + mW + mf * 16 + r4 + half * 8;
            float bv = (EPI == 0) ? bias[m] : 0.f;
#pragma unroll
            for (int nf = 0; nf < NF; ++nf) {
                long n = nBase + nW + nf * 8 + 2 * c4;
                float v0 = acc[mf][nf][half * 2 + 0];
                float v1 = acc[mf][nf][half * 2 + 1];
                if (EPI == 0) {
                    v0 += bv; v1 += bv;
                    if (!mask[(long)mb * maskLd + n]) v0 = 0.f;
                    if (!mask[(long)mb * maskLd + n + 1]) v1 = 0.f;
                    if (res) {
                        v0 += res[z * resStride + m * ldc + n];
                        v1 += res[z * resStride + m * ldc + n + 1];
                    }
                } else if (EPI == 3) {
                    v0 = mask[(long)mb * maskLd + n] ? to_tf32(__expf(v0)) : 0.f;
                    v1 = mask[(long)mb * maskLd + n + 1] ? to_tf32(__expf(v1)) : 0.f;
                } else {
                    v0 = to_tf32(v0); v1 = to_tf32(v1);
                }
                float2 o; o.x = v0; o.y = v1;
                *(float2*)&C[m * ldc + n] = o;
            }
        }
    }
}

// ---------------- mask canonicalization (bool-bytes or int32), both masks ----------------
__global__ void canon_mask_kernel(const unsigned char* __restrict__ raw0,
                                  const unsigned char* __restrict__ raw1,
                                  unsigned char* __restrict__ out0,
                                  unsigned char* __restrict__ out1, int n) {
    const unsigned char* raw = blockIdx.y ? raw1 : raw0;
    unsigned char* out = blockIdx.y ? out1 : out0;
    __shared__ int s_flag;
    if (threadIdx.x == 0) s_flag = 0;
    __syncthreads();
    int local = 0;
    for (int i = threadIdx.x; i < n; i += blockDim.x)
        if ((i & 3) != 0 && raw[i] != 0) local = 1;
    if (local) atomicOr(&s_flag, 1);
    __syncthreads();
    bool is_bool = (s_flag != 0);
    for (int i = threadIdx.x; i < n; i += blockDim.x)
        out[i] = is_bool ? raw[i] : raw[4 * i];
}

// ---------------- tf32 rounding copy (x and ctx in one launch) ----------------
__global__ void round_kernel(const float* __restrict__ inx, float* __restrict__ outx, int n4x,
                             const float* __restrict__ inc, float* __restrict__ outc, int n4c) {
    int i = blockIdx.x * blockDim.x + threadIdx.x;
    const float* in; float* out; int j;
    if (i < n4x) { in = inx; out = outx; j = i; }
    else if (i < n4x + n4c) { in = inc; out = outc; j = i - n4x; }
    else return;
    float4 v = ((const float4*)in)[j];
    v.x = to_tf32(v.x); v.y = to_tf32(v.y); v.z = to_tf32(v.z); v.w = to_tf32(v.w);
    ((float4*)out)[j] = v;
}

// ---------------- bias concat ----------------
__global__ void concat_bias_kernel(const float* __restrict__ a, const float* __restrict__ b,
                                   float* __restrict__ out) {
    int i = blockIdx.x * blockDim.x + threadIdx.x;
    out[i] = (i < EDIM) ? a[i] : b[i - EDIM];
}

// ---------------- weight standardization, all 4 weights in one launch ----------------
__global__ void ws_kernel(const float* __restrict__ qw, const float* __restrict__ kw,
                          const float* __restrict__ vw, const float* __restrict__ ow,
                          float* __restrict__ wnq, float* __restrict__ wnkv,
                          float* __restrict__ wno) {
    int c = blockIdx.y;
    const float* w; float* outp; int I;
    if (c == 0) { w = qw; outp = wnq; I = EDIM; }
    else if (c == 1) { w = kw; outp = wnkv; I = CDIM; }
    else if (c == 2) { w = vw; outp = wnkv + EDIM * CDIM; I = CDIM; }
    else { w = ow; outp = wno; I = EDIM; }
    int o = blockIdx.x;
    const float* row = w + (long)o * I;
    float s = 0.f, ss = 0.f;
    for (int i = threadIdx.x; i < I; i += 256) {
        float v = row[i];
        s += v; ss += v * v;
    }
#pragma unroll
    for (int off = 16; off; off >>= 1) {
        s += __shfl_xor_sync(0xFFFFFFFFu, s, off);
        ss += __shfl_xor_sync(0xFFFFFFFFu, ss, off);
    }
    __shared__ float sh[16];
    int wid = threadIdx.x >> 5;
    if ((threadIdx.x & 31) == 0) { sh[wid] = s; sh[8 + wid] = ss; }
    __syncthreads();
    if (threadIdx.x == 0) {
        float ts = 0.f, tss = 0.f;
        for (int i = 0; i < 8; i++) { ts += sh[i]; tss += sh[8 + i]; }
        float mu = ts / (float)I;
        float var = tss / (float)I - mu * mu;
        sh[0] = mu; sh[1] = rsqrtf(var + EPSV);
    }
    __syncthreads();
    float mu = sh[0], inv = sh[1];
    for (int i = threadIdx.x; i < I; i += 256)
        outp[(long)o * I + i] = to_tf32((row[i] - mu) * inv);
}

// ---------------- per-head LayerNorm over dh=64, q/k/v in one launch ----------------
// q gets an extra 1/256 scale (exact exponent shift) to fold the score scaling.
__global__ void ln_kernel(float* __restrict__ qbuf, float* __restrict__ kvbuf,
                          const float* __restrict__ gq, const float* __restrict__ bq,
                          const float* __restrict__ gk, const float* __restrict__ bk,
                          const float* __restrict__ gv, const float* __restrict__ bv) {
    int c = blockIdx.y / (BATCH * NH);
    int bh = blockIdx.y % (BATCH * NH);
    float* buf; long zStr; const float *g, *bt; float scale;
    if (c == 0) { buf = qbuf; zStr = (long)EDIM * TLEN; g = gq; bt = bq; scale = 1.f / 256.f; }
    else if (c == 1) { buf = kvbuf; zStr = (long)2 * EDIM * SLEN; g = gk; bt = bk; scale = 1.f; }
    else { buf = kvbuf + EDIM * SLEN; zStr = (long)2 * EDIM * SLEN; g = gv; bt = bv; scale = 1.f; }
    int L = TLEN;
    int l = blockIdx.x * blockDim.x + threadIdx.x;
    float* base = buf + (long)(bh / NH) * zStr + (long)(bh % NH) * DH * L + l;
    float vals[DH];
    float s = 0.f, ss = 0.f;
#pragma unroll
    for (int d = 0; d < DH; d++) {
        float v = base[(long)d * L];
        vals[d] = v;
        s += v; ss += v * v;
    }
    float mu = s * (1.f / DH);
    float var = ss * (1.f / DH) - mu * mu;
    float inv = rsqrtf(var + EPSV);
#pragma unroll
    for (int d = 0; d < DH; d++)
        base[(long)d * L] = to_tf32(((vals[d] - mu) * inv * g[d] + bt[d]) * scale);
}

// ---------------- rowsum: r[b,h,s] = mctx[s] && sum>0 ? 1/sum_t e[s,t] : 0 ----------------
__global__ void rowsum_kernel(const float* __restrict__ e, float* __restrict__ r,
                              const unsigned char* __restrict__ mctx) {
    int wid = threadIdx.x >> 5, lane = threadIdx.x & 31;
    long row = (long)blockIdx.x * 8 + wid;
    const float* p = e + row * TLEN;
    float s = 0.f;
#pragma unroll
    for (int j = 0; j < 8; ++j) {
        float4 v = *(const float4*)&p[j * 128 + lane * 4];
        s += v.x + v.y + v.z + v.w;
    }
#pragma unroll
    for (int off = 16; off; off >>= 1)
        s += __shfl_xor_sync(0xFFFFFFFFu, s, off);
    if (lane == 0) {
        int b = (int)(row / (NH * SLEN));
        int sidx = (int)(row % SLEN);
        r[row] = (mctx[(long)b * SLEN + sidx] && s > 0.f) ? (1.f / s) : 0.f;
    }
}

// ---------------- v' = tf32(v * r[b,h,s]) in-place ----------------
__global__ void vscale_kernel(float* __restrict__ kvbuf, const float* __restrict__ r) {
    long i = (long)blockIdx.x * blockDim.x + threadIdx.x;   // float4 index over [B][E][S]
    long fi = i * 4;
    int b = (int)(fi / ((long)EDIM * SLEN));
    long rem = fi % ((long)EDIM * SLEN);
    int e = (int)(rem / SLEN), s = (int)(rem % SLEN);
    int h = e / DH;
    float* vp = kvbuf + (long)b * 2 * EDIM * SLEN + (long)(EDIM + e) * SLEN + s;
    float4 rv = *(const float4*)&r[((long)b * NH + h) * SLEN + s];
    float4 v = *(float4*)vp;
    v.x = to_tf32(v.x * rv.x); v.y = to_tf32(v.y * rv.y);
    v.z = to_tf32(v.z * rv.z); v.w = to_tf32(v.w * rv.w);
    *(float4*)vp = v;
}

// ---------------- launch ----------------
extern "C" void kernel_launch(void* const* d_in, const int* in_sizes, int n_in,
                              void* d_out, int out_size) {
    const float* x = (const float*)d_in[0];
    const float* ctx = (const float*)d_in[1];
    const unsigned char* mask_raw = (const unsigned char*)d_in[2];
    const unsigned char* mctx_raw = (const unsigned char*)d_in[3];
    const float* qw = (const float*)d_in[4];
    const float* qb = (const float*)d_in[5];
    const float* kw = (const float*)d_in[6];
    const float* kb = (const float*)d_in[7];
    const float* vw = (const float*)d_in[8];
    const float* vb = (const float*)d_in[9];
    const float* ow = (const float*)d_in[10];
    const float* ob = (const float*)d_in[11];
    const float* gq = (const float*)d_in[12];
    const float* bq = (const float*)d_in[13];
    const float* gk = (const float*)d_in[14];
    const float* bk = (const float*)d_in[15];
    const float* gv = (const float*)d_in[16];
    const float* bv = (const float*)d_in[17];
    float* out = (float*)d_out;

    float *wnq, *wnkv, *wno, *kvb, *xr, *cr, *qbuf, *kvbuf, *pbuf, *rbuf, *abuf;
    unsigned char *mask, *mctx;
    cudaGetSymbolAddress((void**)&wnq, g_wnq);
    cudaGetSymbolAddress((void**)&wnkv, g_wnkv);
    cudaGetSymbolAddress((void**)&wno, g_wno);
    cudaGetSymbolAddress((void**)&kvb, g_kvb);
    cudaGetSymbolAddress((void**)&xr, g_xr);
    cudaGetSymbolAddress((void**)&cr, g_cr);
    cudaGetSymbolAddress((void**)&qbuf, g_q);
    cudaGetSymbolAddress((void**)&kvbuf, g_kv);
    cudaGetSymbolAddress((void**)&pbuf, g_p);
    cudaGetSymbolAddress((void**)&rbuf, g_r);
    cudaGetSymbolAddress((void**)&abuf, g_att);
    cudaGetSymbolAddress((void**)&mask, g_mask);
    cudaGetSymbolAddress((void**)&mctx, g_mctx);

    const int SM_QKV = 3 * (128 * 36 + 32 * 136) * 4;   // 107520
    const int SM_SC = 3 * (32 * 136 + 32 * 136) * 4;    // 104448
    const int SM_AV = 3 * (32 * 136 + 64 * 36) * 4;     // 79872
    const int SM_OP = 3 * (128 * 36 + 128 * 36) * 4;    // 110592
    cudaFuncSetAttribute((const void*)mma_gemm<0, false, true, 128>,
                         cudaFuncAttributeMaxDynamicSharedMemorySize, SM_QKV);
    cudaFuncSetAttribute((const void*)mma_gemm<3, true, true, 128>,
                         cudaFuncAttributeMaxDynamicSharedMemorySize, SM_SC);
    cudaFuncSetAttribute((const void*)mma_gemm<2, true, false, 64>,
                         cudaFuncAttributeMaxDynamicSharedMemorySize, SM_AV);
    cudaFuncSetAttribute((const void*)mma_gemm<0, false, false, 128>,
                         cudaFuncAttributeMaxDynamicSharedMemorySize, SM_OP);

    // 0. canonicalize masks; round inputs; concat kv bias
    canon_mask_kernel<<<dim3(1, 2), 256>>>(mask_raw, mctx_raw, mask, mctx, BATCH * TLEN);
    const int n4x = BATCH * EDIM * TLEN / 4, n4c = BATCH * CDIM * SLEN / 4;
    round_kernel<<<(n4x + n4c + 255) / 256, 256>>>(x, xr, n4x, ctx, cr, n4c);
    concat_bias_kernel<<<8, 256>>>(kb, vb, kvb);

    // 1. weight standardization (all four, rounded)
    ws_kernel<<<dim3(EDIM, 4), 256>>>(qw, kw, vw, ow, wnq, wnkv, wno);

    // 2a. Q projection
    dim3 gq_(TLEN / 128, EDIM / 128, BATCH);
    mma_gemm<0, false, true, 128><<<gq_, 256, SM_QKV>>>(
        wnq, 1, 0, 0, EDIM,
        xr, 1, (long)EDIM * TLEN, 0, TLEN,
        qbuf, 1, (long)EDIM * TLEN, 0, TLEN,
        EDIM, qb, mask, 1, TLEN, nullptr, 0);
    // 2b. merged K|V projection
    dim3 gkv(SLEN / 128, 2 * EDIM / 128, BATCH);
    mma_gemm<0, false, true, 128><<<gkv, 256, SM_QKV>>>(
        wnkv, 1, 0, 0, CDIM,
        cr, 1, (long)CDIM * SLEN, 0, SLEN,
        kvbuf, 1, (long)2 * EDIM * SLEN, 0, SLEN,
        CDIM, kvb, mctx, 1, SLEN, nullptr, 0);

    // 3. per-head LayerNorm over dh (q scaled by 1/256), all in one launch
    ln_kernel<<<dim3(TLEN / 128, 3 * BATCH * NH), 128>>>(qbuf, kvbuf, gq, bq, gk, bk, gv, bv);

    // 4. e[s,t] = mask[t] ? exp(k·q') : 0   (scale pre-folded into q')
    dim3 gsc(TLEN / 128, SLEN / 128, BATCH * NH);
    mma_gemm<3, true, true, 128><<<gsc, 256, SM_SC>>>(
        kvbuf, NH, (long)2 * EDIM * SLEN, (long)DH * SLEN, SLEN,
        qbuf, NH, (long)EDIM * TLEN, (long)DH * TLEN, TLEN,
        pbuf, 1, (long)SLEN * TLEN, 0, TLEN,
        DH, nullptr, mask, NH, TLEN, nullptr, 0);

    // 5. r[b,h,s] = mctx ? 1/rowsum : 0;  v' = v * r
    rowsum_kernel<<<BATCH * NH * SLEN / 8, 256>>>(pbuf, rbuf, mctx);
    vscale_kernel<<<BATCH * EDIM * SLEN / 4 / 256, 256>>>(kvbuf, rbuf);

    // 6. attT[t,d] = sum_s e[s,t] v'[d,s]
    dim3 gav(1, TLEN / 128, BATCH * NH);
    mma_gemm<2, true, false, 64><<<gav, 256, SM_AV>>>(
        pbuf, 1, (long)SLEN * TLEN, 0, TLEN,
        kvbuf + EDIM * SLEN, NH, (long)2 * EDIM * SLEN, (long)DH * SLEN, SLEN,
        abuf, NH, (long)TLEN * EDIM, DH, EDIM,
        SLEN, nullptr, mask, 1, TLEN, nullptr, 0);

    // 7. output projection + residual
    mma_gemm<0, false, false, 128><<<gq_, 256, SM_OP>>>(
        wno, 1, 0, 0, EDIM,
        abuf, 1, (long)TLEN * EDIM, 0, EDIM,
        out, 1, (long)EDIM * TLEN, 0, TLEN,
        EDIM, ob, mask, 1, TLEN, x, (long)EDIM * TLEN);
}

// round 7
// speedup vs baseline: 1.1084x; 1.1084x over previous
#include <cuda_runtime.h>
#include <cstdint>

#define BATCH 4
#define EDIM 1024
#define CDIM 768
#define TLEN 1024
#define SLEN 1024
#define NH 16
#define DH 64
#define EPSV 1e-5f

// ---------------- scratch (static device globals; no allocation) ----------------
__device__ float g_wnq[EDIM * EDIM];
__device__ float g_wnkv[2 * EDIM * CDIM];               // [wnk ; wnv]
__device__ float g_wno[EDIM * EDIM];
__device__ float g_kvb[2 * EDIM];                       // [kb ; vb]
__device__ float g_xr[BATCH * EDIM * TLEN];             // tf32-rounded x
__device__ float g_cr[BATCH * CDIM * SLEN];             // tf32-rounded ctx
__device__ float g_q[BATCH * EDIM * TLEN];
__device__ float g_kv[(long)BATCH * 2 * EDIM * SLEN];   // [B][2E][S]
__device__ float g_p[(long)BATCH * NH * SLEN * TLEN];   // exp(scores) scratch
__device__ float g_rp[BATCH * NH * SLEN * 8];           // per-t-tile row partial sums
__device__ float g_r[BATCH * NH * SLEN];                // 1/rowsum (or 0)
__device__ float g_att[BATCH * EDIM * TLEN];            // att^T: [B][T][E]
__device__ unsigned char g_mask[BATCH * TLEN];
__device__ unsigned char g_mctx[BATCH * SLEN];

__device__ __forceinline__ float to_tf32(float x) {
    float r;
    asm("cvt.rna.tf32.f32 %0, %1;" : "=f"(r) : "f"(x));
    return r;
}
__device__ __forceinline__ uint32_t f2u(float x) { return __float_as_uint(x); }
__device__ __forceinline__ uint32_t smem_u32(const void* p) {
    uint32_t a;
    asm("{ .reg .u64 t; cvta.to.shared.u64 t, %1; cvt.u32.u64 %0, t; }" : "=r"(a) : "l"(p));
    return a;
}
#define CP16(dst, src) asm volatile("cp.async.cg.shared.global [%0], [%1], 16;" :: "r"(dst), "l"(src))
#define CPCOMMIT()     asm volatile("cp.async.commit_group;" ::: "memory")
#define CPWAIT(N)      asm volatile("cp.async.wait_group %0;" :: "n"(N) : "memory")

#define MMA_TF32(d, a, b) \
    asm volatile("mma.sync.aligned.m16n8k8.row.col.f32.tf32.tf32.f32 " \
                 "{%0,%1,%2,%3}, {%4,%5,%6,%7}, {%8,%9}, {%0,%1,%2,%3};" \
                 : "+f"((d)[0]), "+f"((d)[1]), "+f"((d)[2]), "+f"((d)[3]) \
                 : "r"((a)[0]), "r"((a)[1]), "r"((a)[2]), "r"((a)[3]), \
                   "r"((b)[0]), "r"((b)[1]))

// ---------------- GEMM parameter set ----------------
struct GP {
    const float* A; int aDiv; long aStrZa, aStrZb; int lda;
    const float* B; int bDiv; long bStrZa, bStrZb; int ldb;
    float* C; int cDiv; long cStrZa, cStrZb; int ldc;
    int K;
    const float* bias;
    const unsigned char* mask; int maskDiv; int maskLd;
    const float* res; long resStride;
    float* rp;                       // EPI==3 only: row-partial buffer
};

// ================= mma.sync TF32 GEMM body (cp.async NS-stage, conflict-free) =========
// C[m,n] = sum_k A'[m,k] * B'[n,k]
//   A' from src [m,k] (TA=false, smem [m][k] str 36) or [k,m] (TA=true, smem [k][m] str 136)
//   B' from src [n,k] (TB=false, smem [n][k] str 36) or [k,n] (TB=true, smem [k][n] str 136)
// EPI 0: conv (bias + col-mask->0 + optional residual)
// EPI 2: plain + tf32-round on store
// EPI 3: exp-scores (c = mask[n] ? tf32(expf(c)) : 0) + per-row partial sums -> rp
template <int EPI, bool TA, bool TB, int BN, int NS>
__device__ __forceinline__ void gemm_body(const GP& P, int ytile) {
    constexpr int BM = 128;
    constexpr int AFL = TA ? 32 * 136 : BM * 36;
    constexpr int BFL = TB ? 32 * 136 : BN * 36;
    constexpr int STG = AFL + BFL;
    constexpr int WN = BN / 2;
    constexpr int NF = WN / 8;

    extern __shared__ float smf[];
    uint32_t sbase = smem_u32(smf);
    int tid = threadIdx.x, wid = tid >> 5, lane = tid & 31;
    int z = blockIdx.z;
    const float* A = P.A + (z / P.aDiv) * P.aStrZa + (z % P.aDiv) * P.aStrZb;
    const float* B = P.B + (z / P.bDiv) * P.bStrZa + (z % P.bDiv) * P.bStrZb;
    float* C = P.C + (z / P.cDiv) * P.cStrZa + (z % P.cDiv) * P.cStrZb;
    long mBase = (long)ytile * BM, nBase = (long)blockIdx.x * BN;
    int lda = P.lda, ldb = P.ldb, ldc = P.ldc;

    float acc[2][NF][4];
#pragma unroll
    for (int i = 0; i < 2; ++i)
#pragma unroll
        for (int j = 0; j < NF; ++j)
#pragma unroll
            for (int t = 0; t < 4; ++t) acc[i][j][t] = 0.f;

    int nIter = P.K / 32;

    auto issue = [&](int stage, int k0) {
        uint32_t aoff = sbase + stage * STG * 4;
        if (TA) {
#pragma unroll
            for (int r = 0; r < 4; ++r) {
                int lin = tid + 256 * r;
                int k = lin >> 5, mq = (lin & 31) * 4;
                CP16(aoff + (k * 136 + mq) * 4, &A[(long)(k0 + k) * lda + mBase + mq]);
            }
        } else {
#pragma unroll
            for (int r = 0; r < BM / 32; ++r) {
                int lin = tid + 256 * r;
                int m = lin >> 3, kq = (lin & 7) * 4;
                CP16(aoff + (m * 36 + kq) * 4, &A[(mBase + m) * (long)lda + k0 + kq]);
            }
        }
        uint32_t boff = sbase + (stage * STG + AFL) * 4;
        if (TB) {
#pragma unroll
            for (int r = 0; r < 4; ++r) {
                int lin = tid + 256 * r;
                int k = lin >> 5, nq = (lin & 31) * 4;
                CP16(boff + (k * 136 + nq) * 4, &B[(long)(k0 + k) * ldb + nBase + nq]);
            }
        } else {
#pragma unroll
            for (int r = 0; r < BN / 32; ++r) {
                int lin = tid + 256 * r;
                int n = lin >> 3, kq = (lin & 7) * 4;
                CP16(boff + (n * 36 + kq) * 4, &B[(nBase + n) * (long)ldb + k0 + kq]);
            }
        }
    };

    int warpM = wid & 3, warpN = wid >> 2;
    int mW = warpM * 32, nW = warpN * WN;
    int c4 = lane & 3, r4 = lane >> 2;

    auto compute = [&](int stage) {
        const float* As = smf + stage * STG;
        const float* Bs = As + AFL;
#pragma unroll
        for (int kk = 0; kk < 32; kk += 8) {
            uint32_t a[2][4];
#pragma unroll
            for (int mf = 0; mf < 2; ++mf) {
                int m = mW + mf * 16 + r4;
                if (TA) {
                    a[mf][0] = f2u(As[(kk + c4) * 136 + m]);
                    a[mf][1] = f2u(As[(kk + c4) * 136 + m + 8]);
                    a[mf][2] = f2u(As[(kk + c4 + 4) * 136 + m]);
                    a[mf][3] = f2u(As[(kk + c4 + 4) * 136 + m + 8]);
                } else {
                    a[mf][0] = f2u(As[m * 36 + kk + c4]);
                    a[mf][1] = f2u(As[(m + 8) * 36 + kk + c4]);
                    a[mf][2] = f2u(As[m * 36 + kk + c4 + 4]);
                    a[mf][3] = f2u(As[(m + 8) * 36 + kk + c4 + 4]);
                }
            }
            uint32_t b[NF][2];
#pragma unroll
            for (int nf = 0; nf < NF; ++nf) {
                int n = nW + nf * 8 + r4;
                if (TB) {
                    b[nf][0] = f2u(Bs[(kk + c4) * 136 + n]);
                    b[nf][1] = f2u(Bs[(kk + c4 + 4) * 136 + n]);
                } else {
                    b[nf][0] = f2u(Bs[n * 36 + kk + c4]);
                    b[nf][1] = f2u(Bs[n * 36 + kk + c4 + 4]);
                }
            }
#pragma unroll
            for (int mf = 0; mf < 2; ++mf)
#pragma unroll
                for (int nf = 0; nf < NF; ++nf)
                    MMA_TF32(acc[mf][nf], a[mf], b[nf]);
        }
    };

    for (int s = 0; s < NS - 1; ++s) {
        if (s < nIter) issue(s, s * 32);
        CPCOMMIT();
    }
    for (int it = 0; it < nIter; ++it) {
        CPWAIT(NS - 2);
        __syncthreads();
        compute(it % NS);
        __syncthreads();
        int nx = it + NS - 1;
        if (nx < nIter) issue(nx % NS, nx * 32);
        CPCOMMIT();
    }

    // ---- epilogue ----
    int mb = z / P.maskDiv;
    float rsumT[4] = {0.f, 0.f, 0.f, 0.f};
#pragma unroll
    for (int mf = 0; mf < 2; ++mf) {
#pragma unroll
        for (int half = 0; half < 2; ++half) {
            long m = mBase + mW + mf * 16 + r4 + half * 8;
            float bv = (EPI == 0) ? P.bias[m] : 0.f;
#pragma unroll
            for (int nf = 0; nf < NF; ++nf) {
                long n = nBase + nW + nf * 8 + 2 * c4;
                float v0 = acc[mf][nf][half * 2 + 0];
                float v1 = acc[mf][nf][half * 2 + 1];
                if (EPI == 0) {
                    v0 += bv; v1 += bv;
                    if (!P.mask[(long)mb * P.maskLd + n]) v0 = 0.f;
                    if (!P.mask[(long)mb * P.maskLd + n + 1]) v1 = 0.f;
                    if (P.res) {
                        v0 += P.res[z * P.resStride + m * ldc + n];
                        v1 += P.res[z * P.resStride + m * ldc + n + 1];
                    }
                } else if (EPI == 3) {
                    v0 = P.mask[(long)mb * P.maskLd + n] ? to_tf32(__expf(v0)) : 0.f;
                    v1 = P.mask[(long)mb * P.maskLd + n + 1] ? to_tf32(__expf(v1)) : 0.f;
                    rsumT[mf * 2 + half] += v0 + v1;
                } else {
                    v0 = to_tf32(v0); v1 = to_tf32(v1);
                }
                float2 o; o.x = v0; o.y = v1;
                *(float2*)&C[m * ldc + n] = o;
            }
        }
    }
    if (EPI == 3) {
        // reduce each thread's 4 row-partials over the c4 quad, then across warpN via smem
#pragma unroll
        for (int q = 0; q < 4; ++q) {
            float v = rsumT[q];
            v += __shfl_xor_sync(0xFFFFFFFFu, v, 1);
            v += __shfl_xor_sync(0xFFFFFFFFu, v, 2);
            rsumT[q] = v;
        }
        __syncthreads();                 // pipeline smem dead; reuse front as reduction buf
        float* red = smf;                // [2][128]
        if (c4 == 0) {
#pragma unroll
            for (int mf = 0; mf < 2; ++mf)
#pragma unroll
                for (int half = 0; half < 2; ++half) {
                    int rloc = mW + mf * 16 + half * 8 + r4;
                    red[warpN * 128 + rloc] = rsumT[mf * 2 + half];
                }
        }
        __syncthreads();
        if (tid < 128) {
            float s = red[tid] + red[128 + tid];
            P.rp[((long)z * SLEN + mBase + tid) * 8 + blockIdx.x] = s;
        }
    }
}

// kernel wrapper with uniform dual-param-set dispatch on blockIdx.y
template <int EPI, bool TA, bool TB, int BN, int NS>
__global__ __launch_bounds__(256) void mma_gemm(GP p0, GP p1, int ySplit) {
    if ((int)blockIdx.y < ySplit)
        gemm_body<EPI, TA, TB, BN, NS>(p0, blockIdx.y);
    else
        gemm_body<EPI, TA, TB, BN, NS>(p1, blockIdx.y - ySplit);
}

// ---------------- mask canonicalization (bool-bytes or int32), both masks ----------------
__global__ void canon_mask_kernel(const unsigned char* __restrict__ raw0,
                                  const unsigned char* __restrict__ raw1,
                                  unsigned char* __restrict__ out0,
                                  unsigned char* __restrict__ out1, int n) {
    const unsigned char* raw = blockIdx.y ? raw1 : raw0;
    unsigned char* out = blockIdx.y ? out1 : out0;
    __shared__ int s_flag;
    if (threadIdx.x == 0) s_flag = 0;
    __syncthreads();
    int local = 0;
    for (int i = threadIdx.x; i < n; i += blockDim.x)
        if ((i & 3) != 0 && raw[i] != 0) local = 1;
    if (local) atomicOr(&s_flag, 1);
    __syncthreads();
    bool is_bool = (s_flag != 0);
    for (int i = threadIdx.x; i < n; i += blockDim.x)
        out[i] = is_bool ? raw[i] : raw[4 * i];
}

// ---------------- tf32 rounding copy (x and ctx in one launch) ----------------
__global__ void round_kernel(const float* __restrict__ inx, float* __restrict__ outx, int n4x,
                             const float* __restrict__ inc, float* __restrict__ outc, int n4c) {
    int i = blockIdx.x * blockDim.x + threadIdx.x;
    const float* in; float* out; int j;
    if (i < n4x) { in = inx; out = outx; j = i; }
    else if (i < n4x + n4c) { in = inc; out = outc; j = i - n4x; }
    else return;
    float4 v = ((const float4*)in)[j];
    v.x = to_tf32(v.x); v.y = to_tf32(v.y); v.z = to_tf32(v.z); v.w = to_tf32(v.w);
    ((float4*)out)[j] = v;
}

// ---------------- bias concat ----------------
__global__ void concat_bias_kernel(const float* __restrict__ a, const float* __restrict__ b,
                                   float* __restrict__ out) {
    int i = blockIdx.x * blockDim.x + threadIdx.x;
    out[i] = (i < EDIM) ? a[i] : b[i - EDIM];
}

// ---------------- weight standardization, all 4 weights in one launch ----------------
__global__ void ws_kernel(const float* __restrict__ qw, const float* __restrict__ kw,
                          const float* __restrict__ vw, const float* __restrict__ ow,
                          float* __restrict__ wnq, float* __restrict__ wnkv,
                          float* __restrict__ wno) {
    int c = blockIdx.y;
    const float* w; float* outp; int I;
    if (c == 0) { w = qw; outp = wnq; I = EDIM; }
    else if (c == 1) { w = kw; outp = wnkv; I = CDIM; }
    else if (c == 2) { w = vw; outp = wnkv + EDIM * CDIM; I = CDIM; }
    else { w = ow; outp = wno; I = EDIM; }
    int o = blockIdx.x;
    const float* row = w + (long)o * I;
    float s = 0.f, ss = 0.f;
    for (int i = threadIdx.x; i < I; i += 256) {
        float v = row[i];
        s += v; ss += v * v;
    }
#pragma unroll
    for (int off = 16; off; off >>= 1) {
        s += __shfl_xor_sync(0xFFFFFFFFu, s, off);
        ss += __shfl_xor_sync(0xFFFFFFFFu, ss, off);
    }
    __shared__ float sh[16];
    int wid = threadIdx.x >> 5;
    if ((threadIdx.x & 31) == 0) { sh[wid] = s; sh[8 + wid] = ss; }
    __syncthreads();
    if (threadIdx.x == 0) {
        float ts = 0.f, tss = 0.f;
        for (int i = 0; i < 8; i++) { ts += sh[i]; tss += sh[8 + i]; }
        float mu = ts / (float)I;
        float var = tss / (float)I - mu * mu;
        sh[0] = mu; sh[1] = rsqrtf(var + EPSV);
    }
    __syncthreads();
    float mu = sh[0], inv = sh[1];
    for (int i = threadIdx.x; i < I; i += 256)
        outp[(long)o * I + i] = to_tf32((row[i] - mu) * inv);
}

// ---------------- per-head LayerNorm over dh=64, q/k/v in one launch ----------------
// q gets an extra 1/256 scale (exact exponent shift) to fold the score scaling.
__global__ void ln_kernel(float* __restrict__ qbuf, float* __restrict__ kvbuf,
                          const float* __restrict__ gq, const float* __restrict__ bq,
                          const float* __restrict__ gk, const float* __restrict__ bk,
                          const float* __restrict__ gv, const float* __restrict__ bv) {
    int c = blockIdx.y / (BATCH * NH);
    int bh = blockIdx.y % (BATCH * NH);
    float* buf; long zStr; const float *g, *bt; float scale;
    if (c == 0) { buf = qbuf; zStr = (long)EDIM * TLEN; g = gq; bt = bq; scale = 1.f / 256.f; }
    else if (c == 1) { buf = kvbuf; zStr = (long)2 * EDIM * SLEN; g = gk; bt = bk; scale = 1.f; }
    else { buf = kvbuf + EDIM * SLEN; zStr = (long)2 * EDIM * SLEN; g = gv; bt = bv; scale = 1.f; }
    int L = TLEN;
    int l = blockIdx.x * blockDim.x + threadIdx.x;
    float* base = buf + (long)(bh / NH) * zStr + (long)(bh % NH) * DH * L + l;
    float vals[DH];
    float s = 0.f, ss = 0.f;
#pragma unroll
    for (int d = 0; d < DH; d++) {
        float v = base[(long)d * L];
        vals[d] = v;
        s += v; ss += v * v;
    }
    float mu = s * (1.f / DH);
    float var = ss * (1.f / DH) - mu * mu;
    float inv = rsqrtf(var + EPSV);
#pragma unroll
    for (int d = 0; d < DH; d++)
        base[(long)d * L] = to_tf32(((vals[d] - mu) * inv * g[d] + bt[d]) * scale);
}

// ---------------- finalize r: r[i] = mctx && sum>0 ? 1/sum(rp[i][0..7]) : 0 ----------------
__global__ void finalize_r(const float* __restrict__ rp, float* __restrict__ r,
                           const unsigned char* __restrict__ mctx) {
    int i = blockIdx.x * blockDim.x + threadIdx.x;     // 0..65535
    float4 a = ((const float4*)rp)[i * 2];
    float4 b = ((const float4*)rp)[i * 2 + 1];
    float s = ((a.x + a.y) + (a.z + a.w)) + ((b.x + b.y) + (b.z + b.w));
    int bidx = i >> 14, sidx = i & (SLEN - 1);
    r[i] = (mctx[bidx * SLEN + sidx] && s > 0.f) ? (1.f / s) : 0.f;
}

// ---------------- v' = tf32(v * r[b,h,s]) in-place ----------------
__global__ void vscale_kernel(float* __restrict__ kvbuf, const float* __restrict__ r) {
    long i = (long)blockIdx.x * blockDim.x + threadIdx.x;   // float4 index over [B][E][S]
    long fi = i * 4;
    int b = (int)(fi / ((long)EDIM * SLEN));
    long rem = fi % ((long)EDIM * SLEN);
    int e = (int)(rem / SLEN), s = (int)(rem % SLEN);
    int h = e / DH;
    float* vp = kvbuf + (long)b * 2 * EDIM * SLEN + (long)(EDIM + e) * SLEN + s;
    float4 rv = *(const float4*)&r[((long)b * NH + h) * SLEN + s];
    float4 v = *(float4*)vp;
    v.x = to_tf32(v.x * rv.x); v.y = to_tf32(v.y * rv.y);
    v.z = to_tf32(v.z * rv.z); v.w = to_tf32(v.w * rv.w);
    *(float4*)vp = v;
}

// ---------------- launch ----------------
extern "C" void kernel_launch(void* const* d_in, const int* in_sizes, int n_in,
                              void* d_out, int out_size) {
    const float* x = (const float*)d_in[0];
    const float* ctx = (const float*)d_in[1];
    const unsigned char* mask_raw = (const unsigned char*)d_in[2];
    const unsigned char* mctx_raw = (const unsigned char*)d_in[3];
    const float* qw = (const float*)d_in[4];
    const float* qb = (const float*)d_in[5];
    const float* kw = (const float*)d_in[6];
    const float* kb = (const float*)d_in[7];
    const float* vw = (const float*)d_in[8];
    const float* vb = (const float*)d_in[9];
    const float* ow = (const float*)d_in[10];
    const float* ob = (const float*)d_in[11];
    const float* gq = (const float*)d_in[12];
    const float* bq = (const float*)d_in[13];
    const float* gk = (const float*)d_in[14];
    const float* bk = (const float*)d_in[15];
    const float* gv = (const float*)d_in[16];
    const float* bv = (const float*)d_in[17];
    float* out = (float*)d_out;

    float *wnq, *wnkv, *wno, *kvb, *xr, *cr, *qbuf, *kvbuf, *pbuf, *rpbuf, *rbuf, *abuf;
    unsigned char *mask, *mctx;
    cudaGetSymbolAddress((void**)&wnq, g_wnq);
    cudaGetSymbolAddress((void**)&wnkv, g_wnkv);
    cudaGetSymbolAddress((void**)&wno, g_wno);
    cudaGetSymbolAddress((void**)&kvb, g_kvb);
    cudaGetSymbolAddress((void**)&xr, g_xr);
    cudaGetSymbolAddress((void**)&cr, g_cr);
    cudaGetSymbolAddress((void**)&qbuf, g_q);
    cudaGetSymbolAddress((void**)&kvbuf, g_kv);
    cudaGetSymbolAddress((void**)&pbuf, g_p);
    cudaGetSymbolAddress((void**)&rpbuf, g_rp);
    cudaGetSymbolAddress((void**)&rbuf, g_r);
    cudaGetSymbolAddress((void**)&abuf, g_att);
    cudaGetSymbolAddress((void**)&mask, g_mask);
    cudaGetSymbolAddress((void**)&mctx, g_mctx);

    const int SM_PROJ = 3 * (128 * 36 + 32 * 136) * 4;  // 107520
    const int SM_SC = 3 * (32 * 136 + 32 * 136) * 4;    // 104448
    const int SM_AV = 4 * (32 * 136 + 64 * 36) * 4;     // 106496
    const int SM_OP = 3 * (128 * 36 + 128 * 36) * 4;    // 110592
    cudaFuncSetAttribute((const void*)mma_gemm<0, false, true, 128, 3>,
                         cudaFuncAttributeMaxDynamicSharedMemorySize, SM_PROJ);
    cudaFuncSetAttribute((const void*)mma_gemm<3, true, true, 128, 3>,
                         cudaFuncAttributeMaxDynamicSharedMemorySize, SM_SC);
    cudaFuncSetAttribute((const void*)mma_gemm<2, true, false, 64, 4>,
                         cudaFuncAttributeMaxDynamicSharedMemorySize, SM_AV);
    cudaFuncSetAttribute((const void*)mma_gemm<0, false, false, 128, 3>,
                         cudaFuncAttributeMaxDynamicSharedMemorySize, SM_OP);

    // 0. canonicalize masks; round inputs; concat kv bias
    canon_mask_kernel<<<dim3(1, 2), 256>>>(mask_raw, mctx_raw, mask, mctx, BATCH * TLEN);
    const int n4x = BATCH * EDIM * TLEN / 4, n4c = BATCH * CDIM * SLEN / 4;
    round_kernel<<<(n4x + n4c + 255) / 256, 256>>>(x, xr, n4x, ctx, cr, n4c);
    concat_bias_kernel<<<8, 256>>>(kb, vb, kvb);

    // 1. weight standardization (all four, rounded)
    ws_kernel<<<dim3(EDIM, 4), 256>>>(qw, kw, vw, ow, wnq, wnkv, wno);

    // 2. merged Q + KV projections (one launch, y-dispatch: 8 Q-tiles then 16 KV-tiles)
    GP pq = { wnq, 1, 0, 0, EDIM,
              xr, 1, (long)EDIM * TLEN, 0, TLEN,
              qbuf, 1, (long)EDIM * TLEN, 0, TLEN,
              EDIM, qb, mask, 1, TLEN, nullptr, 0, nullptr };
    GP pkv = { wnkv, 1, 0, 0, CDIM,
               cr, 1, (long)CDIM * SLEN, 0, SLEN,
               kvbuf, 1, (long)2 * EDIM * SLEN, 0, SLEN,
               CDIM, kvb, mctx, 1, SLEN, nullptr, 0, nullptr };
    mma_gemm<0, false, true, 128, 3><<<dim3(8, 24, BATCH), 256, SM_PROJ>>>(pq, pkv, 8);

    // 3. per-head LayerNorm over dh (q scaled by 1/256)
    ln_kernel<<<dim3(TLEN / 128, 3 * BATCH * NH), 128>>>(qbuf, kvbuf, gq, bq, gk, bk, gv, bv);

    // 4. e[s,t] = mask[t] ? exp(k·q') : 0, plus per-row partial sums -> rp
    GP psc = { kvbuf, NH, (long)2 * EDIM * SLEN, (long)DH * SLEN, SLEN,
               qbuf, NH, (long)EDIM * TLEN, (long)DH * TLEN, TLEN,
               pbuf, 1, (long)SLEN * TLEN, 0, TLEN,
               DH, nullptr, mask, NH, TLEN, nullptr, 0, rpbuf };
    mma_gemm<3, true, true, 128, 3><<<dim3(TLEN / 128, SLEN / 128, BATCH * NH), 256, SM_SC>>>(
        psc, psc, 1 << 30);

    // 5. finalize r; v' = v * r
    finalize_r<<<BATCH * NH * SLEN / 256, 256>>>(rpbuf, rbuf, mctx);
    vscale_kernel<<<BATCH * EDIM * SLEN / 4 / 256, 256>>>(kvbuf, rbuf);

    // 6. attT[t,d] = sum_s e[s,t] v'[d,s]
    GP pav = { pbuf, 1, (long)SLEN * TLEN, 0, TLEN,
               kvbuf + EDIM * SLEN, NH, (long)2 * EDIM * SLEN, (long)DH * SLEN, SLEN,
               abuf, NH, (long)TLEN * EDIM, DH, EDIM,
               SLEN, nullptr, mask, 1, TLEN, nullptr, 0, nullptr };
    mma_gemm<2, true, false, 64, 4><<<dim3(1, TLEN / 128, BATCH * NH), 256, SM_AV>>>(
        pav, pav, 1 << 30);

    // 7. output projection + residual
    GP pop = { wno, 1, 0, 0, EDIM,
               abuf, 1, (long)TLEN * EDIM, 0, EDIM,
               out, 1, (long)EDIM * TLEN, 0, TLEN,
               EDIM, ob, mask, 1, TLEN, x, (long)EDIM * TLEN, nullptr };
    mma_gemm<0, false, false, 128, 3><<<dim3(TLEN / 128, EDIM / 128, BATCH), 256, SM_OP>>>(
        pop, pop, 1 << 30);
}

// round 8
// speedup vs baseline: 1.1252x; 1.0151x over previous
#include <cuda_runtime.h>
#include <cstdint>

#define BATCH 4
#define EDIM 1024
#define CDIM 768
#define TLEN 1024
#define SLEN 1024
#define NH 16
#define DH 64
#define EPSV 1e-5f

// ---------------- scratch (static device globals; no allocation) ----------------
__device__ float g_wnq[EDIM * EDIM];
__device__ float g_wnkv[2 * EDIM * CDIM];               // [wnk ; wnv]
__device__ float g_wno[EDIM * EDIM];
__device__ float g_kvb[2 * EDIM];                       // [kb ; vb]
__device__ float g_xr[BATCH * EDIM * TLEN];             // tf32-rounded x
__device__ float g_cr[BATCH * CDIM * SLEN];             // tf32-rounded ctx
__device__ float g_q[BATCH * EDIM * TLEN];
__device__ float g_kv[(long)BATCH * 2 * EDIM * SLEN];   // [B][2E][S]
__device__ float g_p[(long)BATCH * NH * SLEN * TLEN];   // exp(scores) scratch
__device__ float g_rp[BATCH * NH * SLEN * 8];           // per-t-tile row partial sums
__device__ float g_r[BATCH * NH * SLEN];                // 1/rowsum (or 0)
__device__ float g_att[BATCH * EDIM * TLEN];            // att^T: [B][T][E]
__device__ unsigned char g_mask[BATCH * TLEN];
__device__ unsigned char g_mctx[BATCH * SLEN];

__device__ __forceinline__ float to_tf32(float x) {
    float r;
    asm("cvt.rna.tf32.f32 %0, %1;" : "=f"(r) : "f"(x));
    return r;
}
__device__ __forceinline__ uint32_t f2u(float x) { return __float_as_uint(x); }
__device__ __forceinline__ uint32_t smem_u32(const void* p) {
    uint32_t a;
    asm("{ .reg .u64 t; cvta.to.shared.u64 t, %1; cvt.u32.u64 %0, t; }" : "=r"(a) : "l"(p));
    return a;
}
#define CP16(dst, src) asm volatile("cp.async.cg.shared.global [%0], [%1], 16;" :: "r"(dst), "l"(src))
#define CPCOMMIT()     asm volatile("cp.async.commit_group;" ::: "memory")
#define CPWAIT(N)      asm volatile("cp.async.wait_group %0;" :: "n"(N) : "memory")

#define MMA_TF32(d, a, b) \
    asm volatile("mma.sync.aligned.m16n8k8.row.col.f32.tf32.tf32.f32 " \
                 "{%0,%1,%2,%3}, {%4,%5,%6,%7}, {%8,%9}, {%0,%1,%2,%3};" \
                 : "+f"((d)[0]), "+f"((d)[1]), "+f"((d)[2]), "+f"((d)[3]) \
                 : "r"((a)[0]), "r"((a)[1]), "r"((a)[2]), "r"((a)[3]), \
                   "r"((b)[0]), "r"((b)[1]))

// ---------------- GEMM parameter set ----------------
struct GP {
    const float* A; int aDiv; long aStrZa, aStrZb; int lda;
    const float* B; int bDiv; long bStrZa, bStrZb; int ldb;
    float* C; int cDiv; long cStrZa, cStrZb; int ldc;
    int K;
    const float* bias;
    const unsigned char* mask; int maskDiv; int maskLd;
    const float* res; long resStride;
    float* rp;                       // EPI==3 only: row-partial buffer
};

// ================= mma.sync TF32 GEMM body (128 threads, 64x64 warp tiles) =========
// C[m,n] = sum_k A'[m,k] * B'[n,k]
//   A' from src [m,k] (TA=false, smem [m][k] str 36) or [k,m] (TA=true, smem [k][BM+8])
//   B' from src [n,k] (TB=false, smem [n][k] str 36) or [k,n] (TB=true, smem [k][BN+8])
// EPI 0: conv (bias + col-mask->0 + optional residual)
// EPI 2: plain + tf32-round on store
// EPI 3: exp-scores (c = mask[n] ? tf32(expf(c)) : 0) + per-row partial sums -> rp
template <int EPI, bool TA, bool TB, int BM, int BN, int NS>
__device__ __forceinline__ void gemm_body(const GP& P, int ytile) {
    constexpr int ASTR = TA ? (BM + 8) : 36;
    constexpr int AFL = TA ? 32 * (BM + 8) : BM * 36;
    constexpr int BSTR = TB ? (BN + 8) : 36;
    constexpr int BFL = TB ? 32 * (BN + 8) : BN * 36;
    constexpr int STG = AFL + BFL;
    constexpr int NWM = BM / 64;               // warps along M (4 warps total)
    constexpr int MF = 4;                      // 64/16
    constexpr int NF = 8;                      // 64/8

    extern __shared__ float smf[];
    uint32_t sbase = smem_u32(smf);
    int tid = threadIdx.x, wid = tid >> 5, lane = tid & 31;
    int z = blockIdx.z;
    const float* A = P.A + (z / P.aDiv) * P.aStrZa + (z % P.aDiv) * P.aStrZb;
    const float* B = P.B + (z / P.bDiv) * P.bStrZa + (z % P.bDiv) * P.bStrZb;
    float* C = P.C + (z / P.cDiv) * P.cStrZa + (z % P.cDiv) * P.cStrZb;
    long mBase = (long)ytile * BM, nBase = (long)blockIdx.x * BN;
    int lda = P.lda, ldb = P.ldb, ldc = P.ldc;

    float acc[MF][NF][4];
#pragma unroll
    for (int i = 0; i < MF; ++i)
#pragma unroll
        for (int j = 0; j < NF; ++j)
#pragma unroll
            for (int t = 0; t < 4; ++t) acc[i][j][t] = 0.f;

    int nIter = P.K / 32;

    auto issue = [&](int stage, int k0) {
        uint32_t aoff = sbase + stage * STG * 4;
        if (TA) {
#pragma unroll
            for (int r = 0; r < BM / 16; ++r) {
                int lin = tid + 128 * r;
                int k = lin / (BM / 4), mq = (lin % (BM / 4)) * 4;
                CP16(aoff + (k * ASTR + mq) * 4, &A[(long)(k0 + k) * lda + mBase + mq]);
            }
        } else {
#pragma unroll
            for (int r = 0; r < BM / 16; ++r) {
                int lin = tid + 128 * r;
                int m = lin >> 3, kq = (lin & 7) * 4;
                CP16(aoff + (m * 36 + kq) * 4, &A[(mBase + m) * (long)lda + k0 + kq]);
            }
        }
        uint32_t boff = sbase + (stage * STG + AFL) * 4;
        if (TB) {
#pragma unroll
            for (int r = 0; r < BN / 16; ++r) {
                int lin = tid + 128 * r;
                int k = lin / (BN / 4), nq = (lin % (BN / 4)) * 4;
                CP16(boff + (k * BSTR + nq) * 4, &B[(long)(k0 + k) * ldb + nBase + nq]);
            }
        } else {
#pragma unroll
            for (int r = 0; r < BN / 16; ++r) {
                int lin = tid + 128 * r;
                int n = lin >> 3, kq = (lin & 7) * 4;
                CP16(boff + (n * 36 + kq) * 4, &B[(nBase + n) * (long)ldb + k0 + kq]);
            }
        }
    };

    int warpM = wid % NWM, warpN = wid / NWM;
    int mW = warpM * 64, nW = warpN * 64;
    int c4 = lane & 3, r4 = lane >> 2;

    auto compute = [&](int stage) {
        const float* As = smf + stage * STG;
        const float* Bs = As + AFL;
#pragma unroll
        for (int kk = 0; kk < 32; kk += 8) {
            uint32_t a[MF][4];
#pragma unroll
            for (int mf = 0; mf < MF; ++mf) {
                int m = mW + mf * 16 + r4;
                if (TA) {
                    a[mf][0] = f2u(As[(kk + c4) * ASTR + m]);
                    a[mf][1] = f2u(As[(kk + c4) * ASTR + m + 8]);
                    a[mf][2] = f2u(As[(kk + c4 + 4) * ASTR + m]);
                    a[mf][3] = f2u(As[(kk + c4 + 4) * ASTR + m + 8]);
                } else {
                    a[mf][0] = f2u(As[m * 36 + kk + c4]);
                    a[mf][1] = f2u(As[(m + 8) * 36 + kk + c4]);
                    a[mf][2] = f2u(As[m * 36 + kk + c4 + 4]);
                    a[mf][3] = f2u(As[(m + 8) * 36 + kk + c4 + 4]);
                }
            }
            uint32_t b[NF][2];
#pragma unroll
            for (int nf = 0; nf < NF; ++nf) {
                int n = nW + nf * 8 + r4;
                if (TB) {
                    b[nf][0] = f2u(Bs[(kk + c4) * BSTR + n]);
                    b[nf][1] = f2u(Bs[(kk + c4 + 4) * BSTR + n]);
                } else {
                    b[nf][0] = f2u(Bs[n * 36 + kk + c4]);
                    b[nf][1] = f2u(Bs[n * 36 + kk + c4 + 4]);
                }
            }
#pragma unroll
            for (int mf = 0; mf < MF; ++mf)
#pragma unroll
                for (int nf = 0; nf < NF; ++nf)
                    MMA_TF32(acc[mf][nf], a[mf], b[nf]);
        }
    };

    for (int s = 0; s < NS - 1; ++s) {
        if (s < nIter) issue(s, s * 32);
        CPCOMMIT();
    }
    for (int it = 0; it < nIter; ++it) {
        CPWAIT(NS - 2);
        __syncthreads();
        compute(it % NS);
        __syncthreads();
        int nx = it + NS - 1;
        if (nx < nIter) issue(nx % NS, nx * 32);
        CPCOMMIT();
    }

    // ---- epilogue ----
    int mb = z / P.maskDiv;
    float rsumT[MF * 2];
#pragma unroll
    for (int q = 0; q < MF * 2; ++q) rsumT[q] = 0.f;
#pragma unroll
    for (int mf = 0; mf < MF; ++mf) {
#pragma unroll
        for (int half = 0; half < 2; ++half) {
            long m = mBase + mW + mf * 16 + r4 + half * 8;
            float bv = (EPI == 0) ? P.bias[m] : 0.f;
#pragma unroll
            for (int nf = 0; nf < NF; ++nf) {
                long n = nBase + nW + nf * 8 + 2 * c4;
                float v0 = acc[mf][nf][half * 2 + 0];
                float v1 = acc[mf][nf][half * 2 + 1];
                if (EPI == 0) {
                    v0 += bv; v1 += bv;
                    if (!P.mask[(long)mb * P.maskLd + n]) v0 = 0.f;
                    if (!P.mask[(long)mb * P.maskLd + n + 1]) v1 = 0.f;
                    if (P.res) {
                        v0 += P.res[z * P.resStride + m * ldc + n];
                        v1 += P.res[z * P.resStride + m * ldc + n + 1];
                    }
                } else if (EPI == 3) {
                    v0 = P.mask[(long)mb * P.maskLd + n] ? to_tf32(__expf(v0)) : 0.f;
                    v1 = P.mask[(long)mb * P.maskLd + n + 1] ? to_tf32(__expf(v1)) : 0.f;
                    rsumT[mf * 2 + half] += v0 + v1;
                } else {
                    v0 = to_tf32(v0); v1 = to_tf32(v1);
                }
                float2 o; o.x = v0; o.y = v1;
                *(float2*)&C[m * ldc + n] = o;
            }
        }
    }
    if (EPI == 3) {
        // reduce each thread's 8 row-partials over the c4 quad, then across warpN via smem
#pragma unroll
        for (int q = 0; q < MF * 2; ++q) {
            float v = rsumT[q];
            v += __shfl_xor_sync(0xFFFFFFFFu, v, 1);
            v += __shfl_xor_sync(0xFFFFFFFFu, v, 2);
            rsumT[q] = v;
        }
        __syncthreads();                 // pipeline smem dead; reuse front as reduction buf
        float* red = smf;                // [2 warpN][BM rows]
        if (c4 == 0) {
#pragma unroll
            for (int mf = 0; mf < MF; ++mf)
#pragma unroll
                for (int half = 0; half < 2; ++half) {
                    int rloc = mW + mf * 16 + half * 8 + r4;
                    red[warpN * BM + rloc] = rsumT[mf * 2 + half];
                }
        }
        __syncthreads();
        if (tid < BM) {
            float s = red[tid] + red[BM + tid];
            P.rp[((long)z * SLEN + mBase + tid) * 8 + blockIdx.x] = s;
        }
    }
}

// kernel wrapper with uniform dual-param-set dispatch on blockIdx.y
template <int EPI, bool TA, bool TB, int BM, int BN, int NS>
__global__ __launch_bounds__(128) void mma_gemm(GP p0, GP p1, int ySplit) {
    if ((int)blockIdx.y < ySplit)
        gemm_body<EPI, TA, TB, BM, BN, NS>(p0, blockIdx.y);
    else
        gemm_body<EPI, TA, TB, BM, BN, NS>(p1, blockIdx.y - ySplit);
}

// ---------------- mask canonicalization (bool-bytes or int32), both masks ----------------
__global__ void canon_mask_kernel(const unsigned char* __restrict__ raw0,
                                  const unsigned char* __restrict__ raw1,
                                  unsigned char* __restrict__ out0,
                                  unsigned char* __restrict__ out1, int n) {
    const unsigned char* raw = blockIdx.y ? raw1 : raw0;
    unsigned char* out = blockIdx.y ? out1 : out0;
    __shared__ int s_flag;
    if (threadIdx.x == 0) s_flag = 0;
    __syncthreads();
    int local = 0;
    for (int i = threadIdx.x; i < n; i += blockDim.x)
        if ((i & 3) != 0 && raw[i] != 0) local = 1;
    if (local) atomicOr(&s_flag, 1);
    __syncthreads();
    bool is_bool = (s_flag != 0);
    for (int i = threadIdx.x; i < n; i += blockDim.x)
        out[i] = is_bool ? raw[i] : raw[4 * i];
}

// ---------------- tf32 rounding copy (x and ctx in one launch) ----------------
__global__ void round_kernel(const float* __restrict__ inx, float* __restrict__ outx, int n4x,
                             const float* __restrict__ inc, float* __restrict__ outc, int n4c) {
    int i = blockIdx.x * blockDim.x + threadIdx.x;
    const float* in; float* out; int j;
    if (i < n4x) { in = inx; out = outx; j = i; }
    else if (i < n4x + n4c) { in = inc; out = outc; j = i - n4x; }
    else return;
    float4 v = ((const float4*)in)[j];
    v.x = to_tf32(v.x); v.y = to_tf32(v.y); v.z = to_tf32(v.z); v.w = to_tf32(v.w);
    ((float4*)out)[j] = v;
}

// ---------------- bias concat ----------------
__global__ void concat_bias_kernel(const float* __restrict__ a, const float* __restrict__ b,
                                   float* __restrict__ out) {
    int i = blockIdx.x * blockDim.x + threadIdx.x;
    out[i] = (i < EDIM) ? a[i] : b[i - EDIM];
}

// ---------------- weight standardization, all 4 weights in one launch ----------------
__global__ void ws_kernel(const float* __restrict__ qw, const float* __restrict__ kw,
                          const float* __restrict__ vw, const float* __restrict__ ow,
                          float* __restrict__ wnq, float* __restrict__ wnkv,
                          float* __restrict__ wno) {
    int c = blockIdx.y;
    const float* w; float* outp; int I;
    if (c == 0) { w = qw; outp = wnq; I = EDIM; }
    else if (c == 1) { w = kw; outp = wnkv; I = CDIM; }
    else if (c == 2) { w = vw; outp = wnkv + EDIM * CDIM; I = CDIM; }
    else { w = ow; outp = wno; I = EDIM; }
    int o = blockIdx.x;
    const float* row = w + (long)o * I;
    float s = 0.f, ss = 0.f;
    for (int i = threadIdx.x; i < I; i += 256) {
        float v = row[i];
        s += v; ss += v * v;
    }
#pragma unroll
    for (int off = 16; off; off >>= 1) {
        s += __shfl_xor_sync(0xFFFFFFFFu, s, off);
        ss += __shfl_xor_sync(0xFFFFFFFFu, ss, off);
    }
    __shared__ float sh[16];
    int wid = threadIdx.x >> 5;
    if ((threadIdx.x & 31) == 0) { sh[wid] = s; sh[8 + wid] = ss; }
    __syncthreads();
    if (threadIdx.x == 0) {
        float ts = 0.f, tss = 0.f;
        for (int i = 0; i < 8; i++) { ts += sh[i]; tss += sh[8 + i]; }
        float mu = ts / (float)I;
        float var = tss / (float)I - mu * mu;
        sh[0] = mu; sh[1] = rsqrtf(var + EPSV);
    }
    __syncthreads();
    float mu = sh[0], inv = sh[1];
    for (int i = threadIdx.x; i < I; i += 256)
        outp[(long)o * I + i] = to_tf32((row[i] - mu) * inv);
}

// ---------------- per-head LayerNorm over dh=64, q/k/v in one launch ----------------
// q gets an extra 1/256 scale (exact exponent shift) to fold the score scaling.
__global__ void ln_kernel(float* __restrict__ qbuf, float* __restrict__ kvbuf,
                          const float* __restrict__ gq, const float* __restrict__ bq,
                          const float* __restrict__ gk, const float* __restrict__ bk,
                          const float* __restrict__ gv, const float* __restrict__ bv) {
    int c = blockIdx.y / (BATCH * NH);
    int bh = blockIdx.y % (BATCH * NH);
    float* buf; long zStr; const float *g, *bt; float scale;
    if (c == 0) { buf = qbuf; zStr = (long)EDIM * TLEN; g = gq; bt = bq; scale = 1.f / 256.f; }
    else if (c == 1) { buf = kvbuf; zStr = (long)2 * EDIM * SLEN; g = gk; bt = bk; scale = 1.f; }
    else { buf = kvbuf + EDIM * SLEN; zStr = (long)2 * EDIM * SLEN; g = gv; bt = bv; scale = 1.f; }
    int L = TLEN;
    int l = blockIdx.x * blockDim.x + threadIdx.x;
    float* base = buf + (long)(bh / NH) * zStr + (long)(bh % NH) * DH * L + l;
    float vals[DH];
    float s = 0.f, ss = 0.f;
#pragma unroll
    for (int d = 0; d < DH; d++) {
        float v = base[(long)d * L];
        vals[d] = v;
        s += v; ss += v * v;
    }
    float mu = s * (1.f / DH);
    float var = ss * (1.f / DH) - mu * mu;
    float inv = rsqrtf(var + EPSV);
#pragma unroll
    for (int d = 0; d < DH; d++)
        base[(long)d * L] = to_tf32(((vals[d] - mu) * inv * g[d] + bt[d]) * scale);
}

// ---------------- finalize r: r[i] = mctx && sum>0 ? 1/sum(rp[i][0..7]) : 0 ----------------
__global__ void finalize_r(const float* __restrict__ rp, float* __restrict__ r,
                           const unsigned char* __restrict__ mctx) {
    int i = blockIdx.x * blockDim.x + threadIdx.x;     // 0..65535
    float4 a = ((const float4*)rp)[i * 2];
    float4 b = ((const float4*)rp)[i * 2 + 1];
    float s = ((a.x + a.y) + (a.z + a.w)) + ((b.x + b.y) + (b.z + b.w));
    int bidx = i >> 14, sidx = i & (SLEN - 1);
    r[i] = (mctx[bidx * SLEN + sidx] && s > 0.f) ? (1.f / s) : 0.f;
}

// ---------------- v' = tf32(v * r[b,h,s]) in-place ----------------
__global__ void vscale_kernel(float* __restrict__ kvbuf, const float* __restrict__ r) {
    long i = (long)blockIdx.x * blockDim.x + threadIdx.x;   // float4 index over [B][E][S]
    long fi = i * 4;
    int b = (int)(fi / ((long)EDIM * SLEN));
    long rem = fi % ((long)EDIM * SLEN);
    int e = (int)(rem / SLEN), s = (int)(rem % SLEN);
    int h = e / DH;
    float* vp = kvbuf + (long)b * 2 * EDIM * SLEN + (long)(EDIM + e) * SLEN + s;
    float4 rv = *(const float4*)&r[((long)b * NH + h) * SLEN + s];
    float4 v = *(float4*)vp;
    v.x = to_tf32(v.x * rv.x); v.y = to_tf32(v.y * rv.y);
    v.z = to_tf32(v.z * rv.z); v.w = to_tf32(v.w * rv.w);
    *(float4*)vp = v;
}

// ---------------- launch ----------------
extern "C" void kernel_launch(void* const* d_in, const int* in_sizes, int n_in,
                              void* d_out, int out_size) {
    const float* x = (const float*)d_in[0];
    const float* ctx = (const float*)d_in[1];
    const unsigned char* mask_raw = (const unsigned char*)d_in[2];
    const unsigned char* mctx_raw = (const unsigned char*)d_in[3];
    const float* qw = (const float*)d_in[4];
    const float* qb = (const float*)d_in[5];
    const float* kw = (const float*)d_in[6];
    const float* kb = (const float*)d_in[7];
    const float* vw = (const float*)d_in[8];
    const float* vb = (const float*)d_in[9];
    const float* ow = (const float*)d_in[10];
    const float* ob = (const float*)d_in[11];
    const float* gq = (const float*)d_in[12];
    const float* bq = (const float*)d_in[13];
    const float* gk = (const float*)d_in[14];
    const float* bk = (const float*)d_in[15];
    const float* gv = (const float*)d_in[16];
    const float* bv = (const float*)d_in[17];
    float* out = (float*)d_out;

    float *wnq, *wnkv, *wno, *kvb, *xr, *cr, *qbuf, *kvbuf, *pbuf, *rpbuf, *rbuf, *abuf;
    unsigned char *mask, *mctx;
    cudaGetSymbolAddress((void**)&wnq, g_wnq);
    cudaGetSymbolAddress((void**)&wnkv, g_wnkv);
    cudaGetSymbolAddress((void**)&wno, g_wno);
    cudaGetSymbolAddress((void**)&kvb, g_kvb);
    cudaGetSymbolAddress((void**)&xr, g_xr);
    cudaGetSymbolAddress((void**)&cr, g_cr);
    cudaGetSymbolAddress((void**)&qbuf, g_q);
    cudaGetSymbolAddress((void**)&kvbuf, g_kv);
    cudaGetSymbolAddress((void**)&pbuf, g_p);
    cudaGetSymbolAddress((void**)&rpbuf, g_rp);
    cudaGetSymbolAddress((void**)&rbuf, g_r);
    cudaGetSymbolAddress((void**)&abuf, g_att);
    cudaGetSymbolAddress((void**)&mask, g_mask);
    cudaGetSymbolAddress((void**)&mctx, g_mctx);

    const int SM_PROJ = 3 * (128 * 36 + 32 * 136) * 4;  // 107520
    const int SM_SC = 3 * (32 * 136 + 32 * 136) * 4;    // 104448
    const int SM_AV = 2 * (32 * 264 + 64 * 36) * 4;     // 86016
    const int SM_OP = 3 * (128 * 36 + 128 * 36) * 4;    // 110592
    cudaFuncSetAttribute((const void*)mma_gemm<0, false, true, 128, 128, 3>,
                         cudaFuncAttributeMaxDynamicSharedMemorySize, SM_PROJ);
    cudaFuncSetAttribute((const void*)mma_gemm<3, true, true, 128, 128, 3>,
                         cudaFuncAttributeMaxDynamicSharedMemorySize, SM_SC);
    cudaFuncSetAttribute((const void*)mma_gemm<2, true, false, 256, 64, 2>,
                         cudaFuncAttributeMaxDynamicSharedMemorySize, SM_AV);
    cudaFuncSetAttribute((const void*)mma_gemm<0, false, false, 128, 128, 3>,
                         cudaFuncAttributeMaxDynamicSharedMemorySize, SM_OP);

    // 0. canonicalize masks; round inputs; concat kv bias
    canon_mask_kernel<<<dim3(1, 2), 256>>>(mask_raw, mctx_raw, mask, mctx, BATCH * TLEN);
    const int n4x = BATCH * EDIM * TLEN / 4, n4c = BATCH * CDIM * SLEN / 4;
    round_kernel<<<(n4x + n4c + 255) / 256, 256>>>(x, xr, n4x, ctx, cr, n4c);
    concat_bias_kernel<<<8, 256>>>(kb, vb, kvb);

    // 1. weight standardization (all four, rounded)
    ws_kernel<<<dim3(EDIM, 4), 256>>>(qw, kw, vw, ow, wnq, wnkv, wno);

    // 2. merged Q + KV projections (one launch, y-dispatch: 8 Q-tiles then 16 KV-tiles)
    GP pq = { wnq, 1, 0, 0, EDIM,
              xr, 1, (long)EDIM * TLEN, 0, TLEN,
              qbuf, 1, (long)EDIM * TLEN, 0, TLEN,
              EDIM, qb, mask, 1, TLEN, nullptr, 0, nullptr };
    GP pkv = { wnkv, 1, 0, 0, CDIM,
               cr, 1, (long)CDIM * SLEN, 0, SLEN,
               kvbuf, 1, (long)2 * EDIM * SLEN, 0, SLEN,
               CDIM, kvb, mctx, 1, SLEN, nullptr, 0, nullptr };
    mma_gemm<0, false, true, 128, 128, 3><<<dim3(8, 24, BATCH), 128, SM_PROJ>>>(pq, pkv, 8);

    // 3. per-head LayerNorm over dh (q scaled by 1/256)
    ln_kernel<<<dim3(TLEN / 128, 3 * BATCH * NH), 128>>>(qbuf, kvbuf, gq, bq, gk, bk, gv, bv);

    // 4. e[s,t] = mask[t] ? exp(k·q') : 0, plus per-row partial sums -> rp
    GP psc = { kvbuf, NH, (long)2 * EDIM * SLEN, (long)DH * SLEN, SLEN,
               qbuf, NH, (long)EDIM * TLEN, (long)DH * TLEN, TLEN,
               pbuf, 1, (long)SLEN * TLEN, 0, TLEN,
               DH, nullptr, mask, NH, TLEN, nullptr, 0, rpbuf };
    mma_gemm<3, true, true, 128, 128, 3><<<dim3(TLEN / 128, SLEN / 128, BATCH * NH), 128, SM_SC>>>(
        psc, psc, 1 << 30);

    // 5. finalize r; v' = v * r
    finalize_r<<<BATCH * NH * SLEN / 256, 256>>>(rpbuf, rbuf, mctx);
    vscale_kernel<<<BATCH * EDIM * SLEN / 4 / 256, 256>>>(kvbuf, rbuf);

    // 6. attT[t,d] = sum_s e[s,t] v'[d,s]   (256x64 tiles)
    GP pav = { pbuf, 1, (long)SLEN * TLEN, 0, TLEN,
               kvbuf + EDIM * SLEN, NH, (long)2 * EDIM * SLEN, (long)DH * SLEN, SLEN,
               abuf, NH, (long)TLEN * EDIM, DH, EDIM,
               SLEN, nullptr, mask, 1, TLEN, nullptr, 0, nullptr };
    mma_gemm<2, true, false, 256, 64, 2><<<dim3(1, TLEN / 256, BATCH * NH), 128, SM_AV>>>(
        pav, pav, 1 << 30);

    // 7. output projection + residual
    GP pop = { wno, 1, 0, 0, EDIM,
               abuf, 1, (long)TLEN * EDIM, 0, EDIM,
               out, 1, (long)EDIM * TLEN, 0, TLEN,
               EDIM, ob, mask, 1, TLEN, x, (long)EDIM * TLEN, nullptr };
    mma_gemm<0, false, false, 128, 128, 3><<<dim3(TLEN / 128, EDIM / 128, BATCH), 128, SM_OP>>>(
        pop, pop, 1 << 30);
}

// round 9
// speedup vs baseline: 1.6477x; 1.4643x over previous
#include <cuda_runtime.h>
#include <cuda_fp16.h>
#include <cstdint>

#define BATCH 4
#define EDIM 1024
#define CDIM 768
#define TLEN 1024
#define SLEN 1024
#define NH 16
#define DH 64
#define EPSV 1e-5f

// ---------------- scratch (static device globals; no allocation) ----------------
__device__ __half g_wnq[EDIM * EDIM];
__device__ __half g_wnkv[2 * EDIM * CDIM];              // [wnk ; wnv]
__device__ __half g_wno[EDIM * EDIM];
__device__ float g_kvb[2 * EDIM];                       // [kb ; vb]
__device__ __half g_xr[BATCH * EDIM * TLEN];            // fp16-rounded x
__device__ __half g_cr[BATCH * CDIM * SLEN];            // fp16-rounded ctx
__device__ __half g_q[BATCH * EDIM * TLEN];
__device__ __half g_kv[(long)BATCH * 2 * EDIM * SLEN];  // [B][2E][S]
__device__ __half g_p[(long)BATCH * NH * SLEN * TLEN];  // exp(scores) scratch (fp16)
__device__ float g_rp[BATCH * NH * SLEN * 8];           // per-t-tile row partial sums
__device__ float g_r[BATCH * NH * SLEN];                // 1/rowsum (or 0)
__device__ __half g_att[BATCH * EDIM * TLEN];           // att^T: [B][T][E]
__device__ unsigned char g_mask[BATCH * TLEN];
__device__ unsigned char g_mctx[BATCH * SLEN];

__device__ __forceinline__ uint32_t smem_u32(const void* p) {
    uint32_t a;
    asm("{ .reg .u64 t; cvta.to.shared.u64 t, %1; cvt.u32.u64 %0, t; }" : "=r"(a) : "l"(p));
    return a;
}
__device__ __forceinline__ uint32_t ldh2(const __half* p) { return *(const uint32_t*)p; }
__device__ __forceinline__ uint32_t ldh_pair(const __half* plo, const __half* phi) {
    uint32_t lo = *(const uint16_t*)plo, hi = *(const uint16_t*)phi;
    return lo | (hi << 16);
}
__device__ __forceinline__ uint32_t packh2(float lo, float hi) {
    __half2 h = __floats2half2_rn(lo, hi);
    return *(uint32_t*)&h;
}
#define CP16(dst, src) asm volatile("cp.async.cg.shared.global [%0], [%1], 16;" :: "r"(dst), "l"(src))
#define CPCOMMIT()     asm volatile("cp.async.commit_group;" ::: "memory")
#define CPWAIT(N)      asm volatile("cp.async.wait_group %0;" :: "n"(N) : "memory")

#define MMA_F16(d, a, b) \
    asm volatile("mma.sync.aligned.m16n8k16.row.col.f32.f16.f16.f32 " \
                 "{%0,%1,%2,%3}, {%4,%5,%6,%7}, {%8,%9}, {%0,%1,%2,%3};" \
                 : "+f"((d)[0]), "+f"((d)[1]), "+f"((d)[2]), "+f"((d)[3]) \
                 : "r"((a)[0]), "r"((a)[1]), "r"((a)[2]), "r"((a)[3]), \
                   "r"((b)[0]), "r"((b)[1]))

// ---------------- GEMM parameter set ----------------
struct GP {
    const void* A; int aDiv; long aStrZa, aStrZb; int lda;
    const void* B; int bDiv; long bStrZa, bStrZb; int ldb;
    void* C; int cDiv; long cStrZa, cStrZb; int ldc;
    int K;
    const float* bias;
    const unsigned char* mask; int maskDiv; int maskLd;
    const float* res; long resStride;
    float* rp;                       // EPI==3 only: row-partial buffer
};

// ================= fp16 mma GEMM body (128 threads, 64x64 warp tiles) =========
// C[m,n] = sum_k A'[m,k] * B'[n,k]   (fp16 operands, fp32 accum)
//   A' from src [m,k] (TA=false, smem [m][k] stride 40) or [k,m] (TA=true, smem [k][BM+8])
//   B' from src [n,k] (TB=false, smem [n][k] stride 40) or [k,n] (TB=true, smem [k][BN+8])
// EPI 0: conv (bias + col-mask->0; + residual when CBYTES==4)
// EPI 2: plain fp16 store
// EPI 3: exp-scores (c = mask[n] ? h(expf(c)) : 0) + per-row partial sums -> rp
template <int EPI, bool TA, bool TB, int BM, int BN, int NS, int CBYTES>
__device__ __forceinline__ void gemm_body(const GP& P, int ytile) {
    constexpr int ASTR = TA ? (BM + 8) : 40;
    constexpr int AFL = TA ? 32 * (BM + 8) : BM * 40;
    constexpr int BSTR = TB ? (BN + 8) : 40;
    constexpr int BFL = TB ? 32 * (BN + 8) : BN * 40;
    constexpr int STG = AFL + BFL;          // halves per stage
    constexpr int NWM = BM / 64;
    constexpr int MF = 4;
    constexpr int NF = 8;

    extern __shared__ char smch[];
    __half* smh = (__half*)smch;
    uint32_t sbase = smem_u32(smch);
    int tid = threadIdx.x, wid = tid >> 5, lane = tid & 31;
    int z = blockIdx.z;
    const __half* A = (const __half*)P.A + (z / P.aDiv) * P.aStrZa + (z % P.aDiv) * P.aStrZb;
    const __half* B = (const __half*)P.B + (z / P.bDiv) * P.bStrZa + (z % P.bDiv) * P.bStrZb;
    long mBase = (long)ytile * BM, nBase = (long)blockIdx.x * BN;
    int lda = P.lda, ldb = P.ldb, ldc = P.ldc;

    float acc[MF][NF][4];
#pragma unroll
    for (int i = 0; i < MF; ++i)
#pragma unroll
        for (int j = 0; j < NF; ++j)
#pragma unroll
            for (int t = 0; t < 4; ++t) acc[i][j][t] = 0.f;

    int nIter = P.K / 32;

    auto issue = [&](int stage, int k0) {
        uint32_t aoff = sbase + stage * STG * 2;
        if (TA) {
#pragma unroll
            for (int r = 0; r < BM / 32; ++r) {
                int lin = tid + 128 * r;
                int k = lin / (BM / 8), mc = (lin % (BM / 8)) * 8;
                CP16(aoff + (k * ASTR + mc) * 2, &A[(long)(k0 + k) * lda + mBase + mc]);
            }
        } else {
#pragma unroll
            for (int r = 0; r < BM / 32; ++r) {
                int lin = tid + 128 * r;
                int m = lin >> 2, kc = (lin & 3) * 8;
                CP16(aoff + (m * 40 + kc) * 2, &A[(mBase + m) * (long)lda + k0 + kc]);
            }
        }
        uint32_t boff = sbase + (stage * STG + AFL) * 2;
        if (TB) {
#pragma unroll
            for (int r = 0; r < BN / 32; ++r) {
                int lin = tid + 128 * r;
                int k = lin / (BN / 8), nc = (lin % (BN / 8)) * 8;
                CP16(boff + (k * BSTR + nc) * 2, &B[(long)(k0 + k) * ldb + nBase + nc]);
            }
        } else {
#pragma unroll
            for (int r = 0; r < BN / 32; ++r) {
                int lin = tid + 128 * r;
                int n = lin >> 2, kc = (lin & 3) * 8;
                CP16(boff + (n * 40 + kc) * 2, &B[(nBase + n) * (long)ldb + k0 + kc]);
            }
        }
    };

    int warpM = wid % NWM, warpN = wid / NWM;
    int mW = warpM * 64, nW = warpN * 64;
    int c4 = lane & 3, r4 = lane >> 2;

    auto compute = [&](int stage) {
        const __half* As = smh + stage * STG;
        const __half* Bs = As + AFL;
#pragma unroll
        for (int kk = 0; kk < 32; kk += 16) {
            uint32_t a[MF][4];
#pragma unroll
            for (int mf = 0; mf < MF; ++mf) {
                int m = mW + mf * 16 + r4;
                if (TA) {
                    int kr = kk + 2 * c4;
                    a[mf][0] = ldh_pair(As + kr * ASTR + m, As + (kr + 1) * ASTR + m);
                    a[mf][1] = ldh_pair(As + kr * ASTR + m + 8, As + (kr + 1) * ASTR + m + 8);
                    a[mf][2] = ldh_pair(As + (kr + 8) * ASTR + m, As + (kr + 9) * ASTR + m);
                    a[mf][3] = ldh_pair(As + (kr + 8) * ASTR + m + 8, As + (kr + 9) * ASTR + m + 8);
                } else {
                    const __half* pa = As + m * 40 + kk + 2 * c4;
                    a[mf][0] = ldh2(pa);
                    a[mf][1] = ldh2(pa + 8 * 40);
                    a[mf][2] = ldh2(pa + 8);
                    a[mf][3] = ldh2(pa + 8 * 40 + 8);
                }
            }
            uint32_t b[NF][2];
#pragma unroll
            for (int nf = 0; nf < NF; ++nf) {
                int n = nW + nf * 8 + r4;
                if (TB) {
                    int kr = kk + 2 * c4;
                    b[nf][0] = ldh_pair(Bs + kr * BSTR + n, Bs + (kr + 1) * BSTR + n);
                    b[nf][1] = ldh_pair(Bs + (kr + 8) * BSTR + n, Bs + (kr + 9) * BSTR + n);
                } else {
                    const __half* pb = Bs + n * 40 + kk + 2 * c4;
                    b[nf][0] = ldh2(pb);
                    b[nf][1] = ldh2(pb + 8);
                }
            }
#pragma unroll
            for (int mf = 0; mf < MF; ++mf)
#pragma unroll
                for (int nf = 0; nf < NF; ++nf)
                    MMA_F16(acc[mf][nf], a[mf], b[nf]);
        }
    };

    for (int s = 0; s < NS - 1; ++s) {
        if (s < nIter) issue(s, s * 32);
        CPCOMMIT();
    }
    for (int it = 0; it < nIter; ++it) {
        CPWAIT(NS - 2);
        __syncthreads();
        compute(it % NS);
        __syncthreads();
        int nx = it + NS - 1;
        if (nx < nIter) issue(nx % NS, nx * 32);
        CPCOMMIT();
    }

    // ---- epilogue ----
    int mb = z / P.maskDiv;
    float rsumT[MF * 2];
#pragma unroll
    for (int q = 0; q < MF * 2; ++q) rsumT[q] = 0.f;
#pragma unroll
    for (int mf = 0; mf < MF; ++mf) {
#pragma unroll
        for (int half = 0; half < 2; ++half) {
            long m = mBase + mW + mf * 16 + r4 + half * 8;
            float bv = (EPI == 0) ? P.bias[m] : 0.f;
#pragma unroll
            for (int nf = 0; nf < NF; ++nf) {
                long n = nBase + nW + nf * 8 + 2 * c4;
                float v0 = acc[mf][nf][half * 2 + 0];
                float v1 = acc[mf][nf][half * 2 + 1];
                if (EPI == 0) {
                    v0 += bv; v1 += bv;
                    if (!P.mask[(long)mb * P.maskLd + n]) v0 = 0.f;
                    if (!P.mask[(long)mb * P.maskLd + n + 1]) v1 = 0.f;
                } else if (EPI == 3) {
                    __half h0 = __float2half_rn(__expf(v0));
                    __half h1 = __float2half_rn(__expf(v1));
                    v0 = P.mask[(long)mb * P.maskLd + n] ? __half2float(h0) : 0.f;
                    v1 = P.mask[(long)mb * P.maskLd + n + 1] ? __half2float(h1) : 0.f;
                    rsumT[mf * 2 + half] += v0 + v1;
                }
                if (CBYTES == 4) {
                    float* Cf = (float*)P.C + (z / P.cDiv) * P.cStrZa + (z % P.cDiv) * P.cStrZb;
                    if (EPI == 0 && P.res) {
                        v0 += P.res[z * P.resStride + m * ldc + n];
                        v1 += P.res[z * P.resStride + m * ldc + n + 1];
                    }
                    float2 o; o.x = v0; o.y = v1;
                    *(float2*)&Cf[m * ldc + n] = o;
                } else {
                    __half* Ch = (__half*)P.C + (z / P.cDiv) * P.cStrZa + (z % P.cDiv) * P.cStrZb;
                    *(uint32_t*)&Ch[m * ldc + n] = packh2(v0, v1);
                }
            }
        }
    }
    if (EPI == 3) {
#pragma unroll
        for (int q = 0; q < MF * 2; ++q) {
            float v = rsumT[q];
            v += __shfl_xor_sync(0xFFFFFFFFu, v, 1);
            v += __shfl_xor_sync(0xFFFFFFFFu, v, 2);
            rsumT[q] = v;
        }
        __syncthreads();
        float* red = (float*)smch;
        if (c4 == 0) {
#pragma unroll
            for (int mf = 0; mf < MF; ++mf)
#pragma unroll
                for (int half = 0; half < 2; ++half) {
                    int rloc = mW + mf * 16 + half * 8 + r4;
                    red[warpN * BM + rloc] = rsumT[mf * 2 + half];
                }
        }
        __syncthreads();
        if (tid < BM) {
            float s = red[tid] + red[BM + tid];
            P.rp[((long)z * SLEN + mBase + tid) * 8 + blockIdx.x] = s;
        }
    }
}

template <int EPI, bool TA, bool TB, int BM, int BN, int NS, int CBYTES>
__global__ __launch_bounds__(128) void mma_gemm(GP p0, GP p1, int ySplit) {
    if ((int)blockIdx.y < ySplit)
        gemm_body<EPI, TA, TB, BM, BN, NS, CBYTES>(p0, blockIdx.y);
    else
        gemm_body<EPI, TA, TB, BM, BN, NS, CBYTES>(p1, blockIdx.y - ySplit);
}

// ---------------- mask canonicalization (bool-bytes or int32), both masks ----------------
__global__ void canon_mask_kernel(const unsigned char* __restrict__ raw0,
                                  const unsigned char* __restrict__ raw1,
                                  unsigned char* __restrict__ out0,
                                  unsigned char* __restrict__ out1, int n) {
    const unsigned char* raw = blockIdx.y ? raw1 : raw0;
    unsigned char* out = blockIdx.y ? out1 : out0;
    __shared__ int s_flag;
    if (threadIdx.x == 0) s_flag = 0;
    __syncthreads();
    int local = 0;
    for (int i = threadIdx.x; i < n; i += blockDim.x)
        if ((i & 3) != 0 && raw[i] != 0) local = 1;
    if (local) atomicOr(&s_flag, 1);
    __syncthreads();
    bool is_bool = (s_flag != 0);
    for (int i = threadIdx.x; i < n; i += blockDim.x)
        out[i] = is_bool ? raw[i] : raw[4 * i];
}

// ---------------- fp16 rounding copy (x and ctx in one launch) ----------------
__global__ void round_kernel(const float* __restrict__ inx, __half* __restrict__ outx, int n4x,
                             const float* __restrict__ inc, __half* __restrict__ outc, int n4c) {
    int i = blockIdx.x * blockDim.x + threadIdx.x;
    const float* in; __half* out; int j;
    if (i < n4x) { in = inx; out = outx; j = i; }
    else if (i < n4x + n4c) { in = inc; out = outc; j = i - n4x; }
    else return;
    float4 v = ((const float4*)in)[j];
    uint2 o;
    o.x = packh2(v.x, v.y);
    o.y = packh2(v.z, v.w);
    ((uint2*)out)[j] = o;
}

// ---------------- bias concat ----------------
__global__ void concat_bias_kernel(const float* __restrict__ a, const float* __restrict__ b,
                                   float* __restrict__ out) {
    int i = blockIdx.x * blockDim.x + threadIdx.x;
    out[i] = (i < EDIM) ? a[i] : b[i - EDIM];
}

// ---------------- weight standardization, all 4 weights in one launch ----------------
__global__ void ws_kernel(const float* __restrict__ qw, const float* __restrict__ kw,
                          const float* __restrict__ vw, const float* __restrict__ ow,
                          __half* __restrict__ wnq, __half* __restrict__ wnkv,
                          __half* __restrict__ wno) {
    int c = blockIdx.y;
    const float* w; __half* outp; int I;
    if (c == 0) { w = qw; outp = wnq; I = EDIM; }
    else if (c == 1) { w = kw; outp = wnkv; I = CDIM; }
    else if (c == 2) { w = vw; outp = wnkv + EDIM * CDIM; I = CDIM; }
    else { w = ow; outp = wno; I = EDIM; }
    int o = blockIdx.x;
    const float* row = w + (long)o * I;
    float s = 0.f, ss = 0.f;
    for (int i = threadIdx.x; i < I; i += 256) {
        float v = row[i];
        s += v; ss += v * v;
    }
#pragma unroll
    for (int off = 16; off; off >>= 1) {
        s += __shfl_xor_sync(0xFFFFFFFFu, s, off);
        ss += __shfl_xor_sync(0xFFFFFFFFu, ss, off);
    }
    __shared__ float sh[16];
    int wid = threadIdx.x >> 5;
    if ((threadIdx.x & 31) == 0) { sh[wid] = s; sh[8 + wid] = ss; }
    __syncthreads();
    if (threadIdx.x == 0) {
        float ts = 0.f, tss = 0.f;
        for (int i = 0; i < 8; i++) { ts += sh[i]; tss += sh[8 + i]; }
        float mu = ts / (float)I;
        float var = tss / (float)I - mu * mu;
        sh[0] = mu; sh[1] = rsqrtf(var + EPSV);
    }
    __syncthreads();
    float mu = sh[0], inv = sh[1];
    for (int i = threadIdx.x; i < I; i += 256)
        outp[(long)o * I + i] = __float2half_rn((row[i] - mu) * inv);
}

// ---------------- per-head LayerNorm over dh=64, q/k/v in one launch ----------------
// q gets an extra 1/256 scale (exact exponent shift) to fold the score scaling.
__global__ void ln_kernel(__half* __restrict__ qbuf, __half* __restrict__ kvbuf,
                          const float* __restrict__ gq, const float* __restrict__ bq,
                          const float* __restrict__ gk, const float* __restrict__ bk,
                          const float* __restrict__ gv, const float* __restrict__ bv) {
    int c = blockIdx.y / (BATCH * NH);
    int bh = blockIdx.y % (BATCH * NH);
    __half* buf; long zStr; const float *g, *bt; float scale;
    if (c == 0) { buf = qbuf; zStr = (long)EDIM * TLEN; g = gq; bt = bq; scale = 1.f / 256.f; }
    else if (c == 1) { buf = kvbuf; zStr = (long)2 * EDIM * SLEN; g = gk; bt = bk; scale = 1.f; }
    else { buf = kvbuf + EDIM * SLEN; zStr = (long)2 * EDIM * SLEN; g = gv; bt = bv; scale = 1.f; }
    int L = TLEN;
    int l = blockIdx.x * blockDim.x + threadIdx.x;
    __half* base = buf + (long)(bh / NH) * zStr + (long)(bh % NH) * DH * L + l;
    float vals[DH];
    float s = 0.f, ss = 0.f;
#pragma unroll
    for (int d = 0; d < DH; d++) {
        float v = __half2float(base[(long)d * L]);
        vals[d] = v;
        s += v; ss += v * v;
    }
    float mu = s * (1.f / DH);
    float var = ss * (1.f / DH) - mu * mu;
    float inv = rsqrtf(var + EPSV);
#pragma unroll
    for (int d = 0; d < DH; d++)
        base[(long)d * L] = __float2half_rn(((vals[d] - mu) * inv * g[d] + bt[d]) * scale);
}

// ---------------- finalize r: r[i] = mctx && sum>0 ? 1/sum(rp[i][0..7]) : 0 ----------------
__global__ void finalize_r(const float* __restrict__ rp, float* __restrict__ r,
                           const unsigned char* __restrict__ mctx) {
    int i = blockIdx.x * blockDim.x + threadIdx.x;     // 0..65535
    float4 a = ((const float4*)rp)[i * 2];
    float4 b = ((const float4*)rp)[i * 2 + 1];
    float s = ((a.x + a.y) + (a.z + a.w)) + ((b.x + b.y) + (b.z + b.w));
    int bidx = i >> 14, sidx = i & (SLEN - 1);
    r[i] = (mctx[bidx * SLEN + sidx] && s > 0.f) ? (1.f / s) : 0.f;
}

// ---------------- v' = h(v * r[b,h,s]) in-place (fp16) ----------------
__global__ void vscale_kernel(__half* __restrict__ kvbuf, const float* __restrict__ r) {
    long i = (long)blockIdx.x * blockDim.x + threadIdx.x;   // 4-half groups over [B][E][S]
    long fi = i * 4;
    int b = (int)(fi / ((long)EDIM * SLEN));
    long rem = fi % ((long)EDIM * SLEN);
    int e = (int)(rem / SLEN), s = (int)(rem % SLEN);
    int h = e / DH;
    __half* vp = kvbuf + (long)b * 2 * EDIM * SLEN + (long)(EDIM + e) * SLEN + s;
    float4 rv = *(const float4*)&r[((long)b * NH + h) * SLEN + s];
    uint2 v = *(uint2*)vp;
    __half2 v01 = *(__half2*)&v.x, v23 = *(__half2*)&v.y;
    uint2 o;
    o.x = packh2(__half2float(v01.x) * rv.x, __half2float(v01.y) * rv.y);
    o.y = packh2(__half2float(v23.x) * rv.z, __half2float(v23.y) * rv.w);
    *(uint2*)vp = o;
}

// ---------------- launch ----------------
extern "C" void kernel_launch(void* const* d_in, const int* in_sizes, int n_in,
                              void* d_out, int out_size) {
    const float* x = (const float*)d_in[0];
    const float* ctx = (const float*)d_in[1];
    const unsigned char* mask_raw = (const unsigned char*)d_in[2];
    const unsigned char* mctx_raw = (const unsigned char*)d_in[3];
    const float* qw = (const float*)d_in[4];
    const float* qb = (const float*)d_in[5];
    const float* kw = (const float*)d_in[6];
    const float* kb = (const float*)d_in[7];
    const float* vw = (const float*)d_in[8];
    const float* vb = (const float*)d_in[9];
    const float* ow = (const float*)d_in[10];
    const float* ob = (const float*)d_in[11];
    const float* gq = (const float*)d_in[12];
    const float* bq = (const float*)d_in[13];
    const float* gk = (const float*)d_in[14];
    const float* bk = (const float*)d_in[15];
    const float* gv = (const float*)d_in[16];
    const float* bv = (const float*)d_in[17];
    float* out = (float*)d_out;

    __half *wnq, *wnkv, *wno, *xr, *cr, *qbuf, *kvbuf, *pbuf, *abuf;
    float *kvb, *rpbuf, *rbuf;
    unsigned char *mask, *mctx;
    cudaGetSymbolAddress((void**)&wnq, g_wnq);
    cudaGetSymbolAddress((void**)&wnkv, g_wnkv);
    cudaGetSymbolAddress((void**)&wno, g_wno);
    cudaGetSymbolAddress((void**)&kvb, g_kvb);
    cudaGetSymbolAddress((void**)&xr, g_xr);
    cudaGetSymbolAddress((void**)&cr, g_cr);
    cudaGetSymbolAddress((void**)&qbuf, g_q);
    cudaGetSymbolAddress((void**)&kvbuf, g_kv);
    cudaGetSymbolAddress((void**)&pbuf, g_p);
    cudaGetSymbolAddress((void**)&rpbuf, g_rp);
    cudaGetSymbolAddress((void**)&rbuf, g_r);
    cudaGetSymbolAddress((void**)&abuf, g_att);
    cudaGetSymbolAddress((void**)&mask, g_mask);
    cudaGetSymbolAddress((void**)&mctx, g_mctx);

    const int SM_PROJ = 3 * (128 * 40 + 32 * 136) * 2;   // 56832
    const int SM_SC = 3 * (32 * 136 + 32 * 136) * 2;     // 52224
    const int SM_AV = 2 * (32 * 264 + 64 * 40) * 2;      // 44032
    const int SM_OP = 3 * (128 * 40 + 128 * 40) * 2;     // 61440
    cudaFuncSetAttribute((const void*)mma_gemm<0, false, true, 128, 128, 3, 2>,
                         cudaFuncAttributeMaxDynamicSharedMemorySize, SM_PROJ);
    cudaFuncSetAttribute((const void*)mma_gemm<3, true, true, 128, 128, 3, 2>,
                         cudaFuncAttributeMaxDynamicSharedMemorySize, SM_SC);
    cudaFuncSetAttribute((const void*)mma_gemm<2, true, false, 256, 64, 2, 2>,
                         cudaFuncAttributeMaxDynamicSharedMemorySize, SM_AV);
    cudaFuncSetAttribute((const void*)mma_gemm<0, false, false, 128, 128, 3, 4>,
                         cudaFuncAttributeMaxDynamicSharedMemorySize, SM_OP);

    // 0. canonicalize masks; round inputs to fp16; concat kv bias
    canon_mask_kernel<<<dim3(1, 2), 256>>>(mask_raw, mctx_raw, mask, mctx, BATCH * TLEN);
    const int n4x = BATCH * EDIM * TLEN / 4, n4c = BATCH * CDIM * SLEN / 4;
    round_kernel<<<(n4x + n4c + 255) / 256, 256>>>(x, xr, n4x, ctx, cr, n4c);
    concat_bias_kernel<<<8, 256>>>(kb, vb, kvb);

    // 1. weight standardization (all four, fp16 out)
    ws_kernel<<<dim3(EDIM, 4), 256>>>(qw, kw, vw, ow, wnq, wnkv, wno);

    // 2. merged Q + KV projections (one launch)
    GP pq = { wnq, 1, 0, 0, EDIM,
              xr, 1, (long)EDIM * TLEN, 0, TLEN,
              qbuf, 1, (long)EDIM * TLEN, 0, TLEN,
              EDIM, qb, mask, 1, TLEN, nullptr, 0, nullptr };
    GP pkv = { wnkv, 1, 0, 0, CDIM,
               cr, 1, (long)CDIM * SLEN, 0, SLEN,
               kvbuf, 1, (long)2 * EDIM * SLEN, 0, SLEN,
               CDIM, kvb, mctx, 1, SLEN, nullptr, 0, nullptr };
    mma_gemm<0, false, true, 128, 128, 3, 2><<<dim3(8, 24, BATCH), 128, SM_PROJ>>>(pq, pkv, 8);

    // 3. per-head LayerNorm over dh (q scaled by 1/256)
    ln_kernel<<<dim3(TLEN / 128, 3 * BATCH * NH), 128>>>(qbuf, kvbuf, gq, bq, gk, bk, gv, bv);

    // 4. e[s,t] = mask[t] ? exp(k·q') : 0, plus per-row partial sums -> rp
    GP psc = { kvbuf, NH, (long)2 * EDIM * SLEN, (long)DH * SLEN, SLEN,
               qbuf, NH, (long)EDIM * TLEN, (long)DH * TLEN, TLEN,
               pbuf, 1, (long)SLEN * TLEN, 0, TLEN,
               DH, nullptr, mask, NH, TLEN, nullptr, 0, rpbuf };
    mma_gemm<3, true, true, 128, 128, 3, 2><<<dim3(TLEN / 128, SLEN / 128, BATCH * NH), 128, SM_SC>>>(
        psc, psc, 1 << 30);

    // 5. finalize r; v' = v * r
    finalize_r<<<BATCH * NH * SLEN / 256, 256>>>(rpbuf, rbuf, mctx);
    vscale_kernel<<<BATCH * EDIM * SLEN / 4 / 256, 256>>>(kvbuf, rbuf);

    // 6. attT[t,d] = sum_s e[s,t] v'[d,s]   (256x64 tiles)
    GP pav = { pbuf, 1, (long)SLEN * TLEN, 0, TLEN,
               kvbuf + EDIM * SLEN, NH, (long)2 * EDIM * SLEN, (long)DH * SLEN, SLEN,
               abuf, NH, (long)TLEN * EDIM, DH, EDIM,
               SLEN, nullptr, mask, 1, TLEN, nullptr, 0, nullptr };
    mma_gemm<2, true, false, 256, 64, 2, 2><<<dim3(1, TLEN / 256, BATCH * NH), 128, SM_AV>>>(
        pav, pav, 1 << 30);

    // 7. output projection + residual (fp32 out)
    GP pop = { wno, 1, 0, 0, EDIM,
               abuf, 1, (long)TLEN * EDIM, 0, EDIM,
               out, 1, (long)EDIM * TLEN, 0, TLEN,
               EDIM, ob, mask, 1, TLEN, x, (long)EDIM * TLEN, nullptr };
    mma_gemm<0, false, false, 128, 128, 3, 4><<<dim3(TLEN / 128, EDIM / 128, BATCH), 128, SM_OP>>>(
        pop, pop, 1 << 30);
}

// round 10
// speedup vs baseline: 1.7975x; 1.0909x over previous
#include <cuda_runtime.h>
#include <cuda_fp16.h>
#include <cstdint>

#define BATCH 4
#define EDIM 1024
#define CDIM 768
#define TLEN 1024
#define SLEN 1024
#define NH 16
#define DH 64
#define EPSV 1e-5f

// ---------------- scratch (static device globals; no allocation) ----------------
__device__ __half g_wnq[EDIM * EDIM];
__device__ __half g_wnkv[2 * EDIM * CDIM];              // [wnk ; wnv]
__device__ __half g_wno[EDIM * EDIM];
__device__ __half g_xr[BATCH * TLEN * EDIM];            // x^T  [B][T][E] fp16
__device__ __half g_cr[BATCH * SLEN * CDIM];            // ctx^T [B][S][C] fp16
__device__ __half g_q[BATCH * TLEN * EDIM];             // q [B][T][E]
__device__ __half g_k[BATCH * SLEN * EDIM];             // k [B][S][E]
__device__ __half g_v[BATCH * EDIM * SLEN];             // v [B][E][S]
__device__ __half g_p[(long)BATCH * NH * TLEN * SLEN];  // P [b,h][t][s] fp16
__device__ float g_rp[BATCH * NH * SLEN * 8];           // per-t-tile column partials
__device__ float g_r[BATCH * NH * SLEN];                // 1/rowsum (or 0)
__device__ __half g_att[BATCH * TLEN * EDIM];           // att [B][T][E]
__device__ unsigned char g_mask[BATCH * TLEN];
__device__ unsigned char g_mctx[BATCH * SLEN];

__device__ __forceinline__ uint32_t smem_u32(const void* p) {
    uint32_t a;
    asm("{ .reg .u64 t; cvta.to.shared.u64 t, %1; cvt.u32.u64 %0, t; }" : "=r"(a) : "l"(p));
    return a;
}
__device__ __forceinline__ uint32_t ldh2(const __half* p) { return *(const uint32_t*)p; }
__device__ __forceinline__ uint32_t packh2(float lo, float hi) {
    __half2 h = __floats2half2_rn(lo, hi);
    return *(uint32_t*)&h;
}
#define CP16(dst, src) asm volatile("cp.async.cg.shared.global [%0], [%1], 16;" :: "r"(dst), "l"(src))
#define CPCOMMIT()     asm volatile("cp.async.commit_group;" ::: "memory")
#define CPWAIT(N)      asm volatile("cp.async.wait_group %0;" :: "n"(N) : "memory")

#define MMA_F16(d, a, b) \
    asm volatile("mma.sync.aligned.m16n8k16.row.col.f32.f16.f16.f32 " \
                 "{%0,%1,%2,%3}, {%4,%5,%6,%7}, {%8,%9}, {%0,%1,%2,%3};" \
                 : "+f"((d)[0]), "+f"((d)[1]), "+f"((d)[2]), "+f"((d)[3]) \
                 : "r"((a)[0]), "r"((a)[1]), "r"((a)[2]), "r"((a)[3]), \
                   "r"((b)[0]), "r"((b)[1]))

// ---------------- GEMM parameter set ----------------
struct GP {
    const void* A; int aDiv; long aStrZa, aStrZb; int lda;
    const void* B; int bDiv; long bStrZa, bStrZb; int ldb;
    void* C; int cDiv; long cStrZa, cStrZb; int ldc;
    int K;
    const float* bias; int biasOnM;
    const unsigned char* mask; int maskOnM; int maskDiv; int maskLd;
    const float* res; long resStride;
    float* rp;                       // EPI==3 only: column-partial buffer
};

// ================= fp16 mma GEMM body: ALL operands [rows][k] k-contiguous =========
// C[m,n] = sum_k A[m,k] * B[n,k]   (fp16 operands, fp32 accum)
// smem: A [m][k] stride 40, B [n][k] stride 40 (conflict-free, 32-bit frag loads).
// EPI 0: conv (bias on m or n; mask->0 on m or n; + residual when CBYTES==4)
// EPI 2: plain fp16 store
// EPI 3: exp-scores (c = mask[m] ? h(expf(c)) : 0) + per-COLUMN partial sums -> rp
template <int EPI, int BM, int BN, int NS, int CBYTES>
__device__ __forceinline__ void gemm_body(const GP& P, int ytile) {
    constexpr int AFL = BM * 40;
    constexpr int BFL = BN * 40;
    constexpr int STG = AFL + BFL;          // halves per stage
    constexpr int NWM = BM / 64;
    constexpr int MF = 4;
    constexpr int NF = 8;

    extern __shared__ char smch[];
    __half* smh = (__half*)smch;
    uint32_t sbase = smem_u32(smch);
    int tid = threadIdx.x, wid = tid >> 5, lane = tid & 31;
    int z = blockIdx.z;
    const __half* A = (const __half*)P.A + (z / P.aDiv) * P.aStrZa + (z % P.aDiv) * P.aStrZb;
    const __half* B = (const __half*)P.B + (z / P.bDiv) * P.bStrZa + (z % P.bDiv) * P.bStrZb;
    long mBase = (long)ytile * BM, nBase = (long)blockIdx.x * BN;
    int lda = P.lda, ldb = P.ldb, ldc = P.ldc;

    float acc[MF][NF][4];
#pragma unroll
    for (int i = 0; i < MF; ++i)
#pragma unroll
        for (int j = 0; j < NF; ++j)
#pragma unroll
            for (int t = 0; t < 4; ++t) acc[i][j][t] = 0.f;

    int nIter = P.K / 32;

    auto issue = [&](int stage, int k0) {
        uint32_t aoff = sbase + stage * STG * 2;
#pragma unroll
        for (int r = 0; r < BM / 32; ++r) {
            int lin = tid + 128 * r;
            int m = lin >> 2, kc = (lin & 3) * 8;
            CP16(aoff + (m * 40 + kc) * 2, &A[(mBase + m) * (long)lda + k0 + kc]);
        }
        uint32_t boff = sbase + (stage * STG + AFL) * 2;
#pragma unroll
        for (int r = 0; r < BN / 32; ++r) {
            int lin = tid + 128 * r;
            int n = lin >> 2, kc = (lin & 3) * 8;
            CP16(boff + (n * 40 + kc) * 2, &B[(nBase + n) * (long)ldb + k0 + kc]);
        }
    };

    int warpM = wid % NWM, warpN = wid / NWM;
    int mW = warpM * 64, nW = warpN * 64;
    int c4 = lane & 3, r4 = lane >> 2;

    auto compute = [&](int stage) {
        const __half* As = smh + stage * STG;
        const __half* Bs = As + AFL;
#pragma unroll
        for (int kk = 0; kk < 32; kk += 16) {
            uint32_t a[MF][4];
#pragma unroll
            for (int mf = 0; mf < MF; ++mf) {
                const __half* pa = As + (mW + mf * 16 + r4) * 40 + kk + 2 * c4;
                a[mf][0] = ldh2(pa);
                a[mf][1] = ldh2(pa + 8 * 40);
                a[mf][2] = ldh2(pa + 8);
                a[mf][3] = ldh2(pa + 8 * 40 + 8);
            }
            uint32_t b[NF][2];
#pragma unroll
            for (int nf = 0; nf < NF; ++nf) {
                const __half* pb = Bs + (nW + nf * 8 + r4) * 40 + kk + 2 * c4;
                b[nf][0] = ldh2(pb);
                b[nf][1] = ldh2(pb + 8);
            }
#pragma unroll
            for (int mf = 0; mf < MF; ++mf)
#pragma unroll
                for (int nf = 0; nf < NF; ++nf)
                    MMA_F16(acc[mf][nf], a[mf], b[nf]);
        }
    };

    for (int s = 0; s < NS - 1; ++s) {
        if (s < nIter) issue(s, s * 32);
        CPCOMMIT();
    }
    for (int it = 0; it < nIter; ++it) {
        CPWAIT(NS - 2);
        __syncthreads();
        compute(it % NS);
        __syncthreads();
        int nx = it + NS - 1;
        if (nx < nIter) issue(nx % NS, nx * 32);
        CPCOMMIT();
    }

    // ---- epilogue ----
    int mb = z / P.maskDiv;
    // precompute per-n bias/mask when on n
    float bn[NF][2];
    unsigned char mn[NF][2];
    if (EPI == 0) {
#pragma unroll
        for (int nf = 0; nf < NF; ++nf) {
            long n = nBase + nW + nf * 8 + 2 * c4;
            bn[nf][0] = P.biasOnM ? 0.f : P.bias[n];
            bn[nf][1] = P.biasOnM ? 0.f : P.bias[n + 1];
            mn[nf][0] = P.maskOnM ? 1 : P.mask[(long)mb * P.maskLd + n];
            mn[nf][1] = P.maskOnM ? 1 : P.mask[(long)mb * P.maskLd + n + 1];
        }
    }
    float rsumN[NF * 2];
#pragma unroll
    for (int q = 0; q < NF * 2; ++q) rsumN[q] = 0.f;

#pragma unroll
    for (int mf = 0; mf < MF; ++mf) {
#pragma unroll
        for (int half = 0; half < 2; ++half) {
            long m = mBase + mW + mf * 16 + r4 + half * 8;
            float bvm = (EPI == 0 && P.biasOnM) ? P.bias[m] : 0.f;
            bool mOK = true;
            if ((EPI == 0 || EPI == 3) && P.maskOnM)
                mOK = P.mask[(long)mb * P.maskLd + m] != 0;
#pragma unroll
            for (int nf = 0; nf < NF; ++nf) {
                long n = nBase + nW + nf * 8 + 2 * c4;
                float v0 = acc[mf][nf][half * 2 + 0];
                float v1 = acc[mf][nf][half * 2 + 1];
                if (EPI == 0) {
                    if (P.biasOnM) { v0 += bvm; v1 += bvm; }
                    else { v0 += bn[nf][0]; v1 += bn[nf][1]; }
                    if (P.maskOnM) { if (!mOK) { v0 = 0.f; v1 = 0.f; } }
                    else { if (!mn[nf][0]) v0 = 0.f; if (!mn[nf][1]) v1 = 0.f; }
                } else if (EPI == 3) {
                    __half h0 = __float2half_rn(__expf(v0));
                    __half h1 = __float2half_rn(__expf(v1));
                    v0 = mOK ? __half2float(h0) : 0.f;
                    v1 = mOK ? __half2float(h1) : 0.f;
                    rsumN[nf * 2 + 0] += v0;
                    rsumN[nf * 2 + 1] += v1;
                }
                if (CBYTES == 4) {
                    float* Cf = (float*)P.C + (z / P.cDiv) * P.cStrZa + (z % P.cDiv) * P.cStrZb;
                    if (EPI == 0 && P.res) {
                        v0 += P.res[z * P.resStride + m * ldc + n];
                        v1 += P.res[z * P.resStride + m * ldc + n + 1];
                    }
                    float2 o; o.x = v0; o.y = v1;
                    *(float2*)&Cf[m * ldc + n] = o;
                } else {
                    __half* Ch = (__half*)P.C + (z / P.cDiv) * P.cStrZa + (z % P.cDiv) * P.cStrZb;
                    *(uint32_t*)&Ch[m * ldc + n] = packh2(v0, v1);
                }
            }
        }
    }
    if (EPI == 3) {
        // column sums: reduce over r4 lanes (rows), then across warpM warps via smem
#pragma unroll
        for (int q = 0; q < NF * 2; ++q) {
            float v = rsumN[q];
            v += __shfl_xor_sync(0xFFFFFFFFu, v, 4);
            v += __shfl_xor_sync(0xFFFFFFFFu, v, 8);
            v += __shfl_xor_sync(0xFFFFFFFFu, v, 16);
            rsumN[q] = v;
        }
        __syncthreads();
        float* red = (float*)smch;           // [NWM][BN]
        if (r4 == 0) {
#pragma unroll
            for (int nf = 0; nf < NF; ++nf) {
                int nl = nW + nf * 8 + 2 * c4;
                red[warpM * BN + nl] = rsumN[nf * 2 + 0];
                red[warpM * BN + nl + 1] = rsumN[nf * 2 + 1];
            }
        }
        __syncthreads();
        if (tid < BN) {
            float s = red[tid];
#pragma unroll
            for (int w = 1; w < NWM; ++w) s += red[w * BN + tid];
            P.rp[((long)z * SLEN + nBase + tid) * 8 + ytile] = s;
        }
    }
}

// kernel wrapper with uniform triple-param-set dispatch on blockIdx.y
template <int EPI, int BM, int BN, int NS, int CBYTES>
__global__ __launch_bounds__(128) void mma_gemm(GP p0, GP p1, GP p2, int y1, int y2) {
    int y = blockIdx.y;
    if (y < y1) gemm_body<EPI, BM, BN, NS, CBYTES>(p0, y);
    else if (y < y2) gemm_body<EPI, BM, BN, NS, CBYTES>(p1, y - y1);
    else gemm_body<EPI, BM, BN, NS, CBYTES>(p2, y - y2);
}

// ---------------- mask canonicalization (bool-bytes or int32), both masks ----------------
__global__ void canon_mask_kernel(const unsigned char* __restrict__ raw0,
                                  const unsigned char* __restrict__ raw1,
                                  unsigned char* __restrict__ out0,
                                  unsigned char* __restrict__ out1, int n) {
    const unsigned char* raw = blockIdx.y ? raw1 : raw0;
    unsigned char* out = blockIdx.y ? out1 : out0;
    __shared__ int s_flag;
    if (threadIdx.x == 0) s_flag = 0;
    __syncthreads();
    int local = 0;
    for (int i = threadIdx.x; i < n; i += blockDim.x)
        if ((i & 3) != 0 && raw[i] != 0) local = 1;
    if (local) atomicOr(&s_flag, 1);
    __syncthreads();
    bool is_bool = (s_flag != 0);
    for (int i = threadIdx.x; i < n; i += blockDim.x)
        out[i] = is_bool ? raw[i] : raw[4 * i];
}

// ---------------- tiled transpose fp32 -> fp16: in [R][C] -> out [C][R] per batch ----------------
__global__ void transpose_f2h(const float* __restrict__ in, __half* __restrict__ out,
                              int R, int C) {
    __shared__ float tile[32][33];
    int b = blockIdx.z;
    const float* src = in + (long)b * R * C;
    __half* dst = out + (long)b * R * C;
    int c0 = blockIdx.x * 32, r0 = blockIdx.y * 32;
    int tx = threadIdx.x, ty = threadIdx.y;      // 32 x 8
#pragma unroll
    for (int i = 0; i < 32; i += 8)
        tile[ty + i][tx] = src[(long)(r0 + ty + i) * C + c0 + tx];
    __syncthreads();
#pragma unroll
    for (int i = 0; i < 32; i += 8)
        dst[(long)(c0 + ty + i) * R + r0 + tx] = __float2half_rn(tile[tx][ty + i]);
}

// ---------------- weight standardization, all 4 weights in one launch ----------------
__global__ void ws_kernel(const float* __restrict__ qw, const float* __restrict__ kw,
                          const float* __restrict__ vw, const float* __restrict__ ow,
                          __half* __restrict__ wnq, __half* __restrict__ wnkv,
                          __half* __restrict__ wno) {
    int c = blockIdx.y;
    const float* w; __half* outp; int I;
    if (c == 0) { w = qw; outp = wnq; I = EDIM; }
    else if (c == 1) { w = kw; outp = wnkv; I = CDIM; }
    else if (c == 2) { w = vw; outp = wnkv + EDIM * CDIM; I = CDIM; }
    else { w = ow; outp = wno; I = EDIM; }
    int o = blockIdx.x;
    const float* row = w + (long)o * I;
    float s = 0.f, ss = 0.f;
    for (int i = threadIdx.x; i < I; i += 256) {
        float v = row[i];
        s += v; ss += v * v;
    }
#pragma unroll
    for (int off = 16; off; off >>= 1) {
        s += __shfl_xor_sync(0xFFFFFFFFu, s, off);
        ss += __shfl_xor_sync(0xFFFFFFFFu, ss, off);
    }
    __shared__ float sh[16];
    int wid = threadIdx.x >> 5;
    if ((threadIdx.x & 31) == 0) { sh[wid] = s; sh[8 + wid] = ss; }
    __syncthreads();
    if (threadIdx.x == 0) {
        float ts = 0.f, tss = 0.f;
        for (int i = 0; i < 8; i++) { ts += sh[i]; tss += sh[8 + i]; }
        float mu = ts / (float)I;
        float var = tss / (float)I - mu * mu;
        sh[0] = mu; sh[1] = rsqrtf(var + EPSV);
    }
    __syncthreads();
    float mu = sh[0], inv = sh[1];
    for (int i = threadIdx.x; i < I; i += 256)
        outp[(long)o * I + i] = __float2half_rn((row[i] - mu) * inv);
}

// ---------------- per-head LayerNorm over dh=64 ----------------
// c=0: q [B][T][E] contiguous dh (scale 1/256); c=1: k [B][S][E]; c=2: v [B][E][S] strided
__global__ void ln_kernel(__half* __restrict__ qbuf, __half* __restrict__ kbuf,
                          __half* __restrict__ vbuf,
                          const float* __restrict__ gq, const float* __restrict__ bq,
                          const float* __restrict__ gk, const float* __restrict__ bk,
                          const float* __restrict__ gv, const float* __restrict__ bv) {
    int c = blockIdx.y / (BATCH * NH);
    int bh = blockIdx.y % (BATCH * NH);
    int b = bh / NH, h = bh % NH;
    int l = blockIdx.x * blockDim.x + threadIdx.x;
    float vals[DH];
    float s = 0.f, ss = 0.f;
    if (c < 2) {
        __half* base = (c == 0 ? qbuf : kbuf) + ((long)b * TLEN + l) * EDIM + h * DH;
        const float* g = c == 0 ? gq : gk;
        const float* bt = c == 0 ? bq : bk;
        float scale = c == 0 ? (1.f / 256.f) : 1.f;
#pragma unroll
        for (int i = 0; i < 8; ++i) {
            uint4 u = ((const uint4*)base)[i];
            const __half2* hp = (const __half2*)&u;
#pragma unroll
            for (int j = 0; j < 4; ++j) {
                float2 f = __half22float2(hp[j]);
                vals[i * 8 + j * 2] = f.x;
                vals[i * 8 + j * 2 + 1] = f.y;
                s += f.x + f.y;
                ss += f.x * f.x + f.y * f.y;
            }
        }
        float mu = s * (1.f / DH);
        float var = ss * (1.f / DH) - mu * mu;
        float inv = rsqrtf(var + EPSV);
#pragma unroll
        for (int i = 0; i < 8; ++i) {
            uint4 u;
            uint32_t* up = (uint32_t*)&u;
#pragma unroll
            for (int j = 0; j < 4; ++j) {
                int d0 = i * 8 + j * 2;
                up[j] = packh2(((vals[d0] - mu) * inv * g[d0] + bt[d0]) * scale,
                               ((vals[d0 + 1] - mu) * inv * g[d0 + 1] + bt[d0 + 1]) * scale);
            }
            ((uint4*)base)[i] = u;
        }
    } else {
        __half* base = vbuf + (long)b * EDIM * SLEN + (long)h * DH * SLEN + l;
#pragma unroll
        for (int d = 0; d < DH; d++) {
            float v = __half2float(base[(long)d * SLEN]);
            vals[d] = v;
            s += v; ss += v * v;
        }
        float mu = s * (1.f / DH);
        float var = ss * (1.f / DH) - mu * mu;
        float inv = rsqrtf(var + EPSV);
#pragma unroll
        for (int d = 0; d < DH; d++)
            base[(long)d * SLEN] = __float2half_rn((vals[d] - mu) * inv * gv[d] + bv[d]);
    }
}

// ---------------- finalize r: r[i] = mctx && sum>0 ? 1/sum(rp[i][0..7]) : 0 ----------------
__global__ void finalize_r(const float* __restrict__ rp, float* __restrict__ r,
                           const unsigned char* __restrict__ mctx) {
    int i = blockIdx.x * blockDim.x + threadIdx.x;     // 0..65535
    float4 a = ((const float4*)rp)[i * 2];
    float4 b = ((const float4*)rp)[i * 2 + 1];
    float s = ((a.x + a.y) + (a.z + a.w)) + ((b.x + b.y) + (b.z + b.w));
    int bidx = i >> 14, sidx = i & (SLEN - 1);
    r[i] = (mctx[bidx * SLEN + sidx] && s > 0.f) ? (1.f / s) : 0.f;
}

// ---------------- v' = h(v * r[b,h,s]) in-place (fp16) ----------------
__global__ void vscale_kernel(__half* __restrict__ vbuf, const float* __restrict__ r) {
    long i = (long)blockIdx.x * blockDim.x + threadIdx.x;   // 4-half groups over [B][E][S]
    long fi = i * 4;
    int b = (int)(fi / ((long)EDIM * SLEN));
    long rem = fi % ((long)EDIM * SLEN);
    int e = (int)(rem / SLEN), s = (int)(rem % SLEN);
    int h = e / DH;
    __half* vp = vbuf + (long)b * EDIM * SLEN + (long)e * SLEN + s;
    float4 rv = *(const float4*)&r[((long)b * NH + h) * SLEN + s];
    uint2 v = *(uint2*)vp;
    __half2 v01 = *(__half2*)&v.x, v23 = *(__half2*)&v.y;
    uint2 o;
    o.x = packh2(__half2float(v01.x) * rv.x, __half2float(v01.y) * rv.y);
    o.y = packh2(__half2float(v23.x) * rv.z, __half2float(v23.y) * rv.w);
    *(uint2*)vp = o;
}

// ---------------- launch ----------------
extern "C" void kernel_launch(void* const* d_in, const int* in_sizes, int n_in,
                              void* d_out, int out_size) {
    const float* x = (const float*)d_in[0];
    const float* ctx = (const float*)d_in[1];
    const unsigned char* mask_raw = (const unsigned char*)d_in[2];
    const unsigned char* mctx_raw = (const unsigned char*)d_in[3];
    const float* qw = (const float*)d_in[4];
    const float* qb = (const float*)d_in[5];
    const float* kw = (const float*)d_in[6];
    const float* kb = (const float*)d_in[7];
    const float* vw = (const float*)d_in[8];
    const float* vb = (const float*)d_in[9];
    const float* ow = (const float*)d_in[10];
    const float* ob = (const float*)d_in[11];
    const float* gq = (const float*)d_in[12];
    const float* bq = (const float*)d_in[13];
    const float* gk = (const float*)d_in[14];
    const float* bk = (const float*)d_in[15];
    const float* gv = (const float*)d_in[16];
    const float* bv = (const float*)d_in[17];
    float* out = (float*)d_out;

    __half *wnq, *wnkv, *wno, *xr, *cr, *qbuf, *kbuf, *vbuf, *pbuf, *abuf;
    float *rpbuf, *rbuf;
    unsigned char *mask, *mctx;
    cudaGetSymbolAddress((void**)&wnq, g_wnq);
    cudaGetSymbolAddress((void**)&wnkv, g_wnkv);
    cudaGetSymbolAddress((void**)&wno, g_wno);
    cudaGetSymbolAddress((void**)&xr, g_xr);
    cudaGetSymbolAddress((void**)&cr, g_cr);
    cudaGetSymbolAddress((void**)&qbuf, g_q);
    cudaGetSymbolAddress((void**)&kbuf, g_k);
    cudaGetSymbolAddress((void**)&vbuf, g_v);
    cudaGetSymbolAddress((void**)&pbuf, g_p);
    cudaGetSymbolAddress((void**)&rpbuf, g_rp);
    cudaGetSymbolAddress((void**)&rbuf, g_r);
    cudaGetSymbolAddress((void**)&abuf, g_att);
    cudaGetSymbolAddress((void**)&mask, g_mask);
    cudaGetSymbolAddress((void**)&mctx, g_mctx);

    __half* wnk = wnkv;
    __half* wnv = wnkv + EDIM * CDIM;

    const int SM_PROJ = 3 * (128 + 128) * 40 * 2;   // 61440
    const int SM_SC = 3 * (128 + 128) * 40 * 2;     // 61440
    const int SM_AV = 3 * (256 + 64) * 40 * 2;      // 76800
    const int SM_OP = 3 * (128 + 128) * 40 * 2;     // 61440
    cudaFuncSetAttribute((const void*)mma_gemm<0, 128, 128, 3, 2>,
                         cudaFuncAttributeMaxDynamicSharedMemorySize, SM_PROJ);
    cudaFuncSetAttribute((const void*)mma_gemm<3, 128, 128, 3, 2>,
                         cudaFuncAttributeMaxDynamicSharedMemorySize, SM_SC);
    cudaFuncSetAttribute((const void*)mma_gemm<2, 256, 64, 3, 2>,
                         cudaFuncAttributeMaxDynamicSharedMemorySize, SM_AV);
    cudaFuncSetAttribute((const void*)mma_gemm<0, 128, 128, 3, 4>,
                         cudaFuncAttributeMaxDynamicSharedMemorySize, SM_OP);

    // 0. canonicalize masks; transpose+round inputs to fp16
    canon_mask_kernel<<<dim3(1, 2), 256>>>(mask_raw, mctx_raw, mask, mctx, BATCH * TLEN);
    transpose_f2h<<<dim3(TLEN / 32, EDIM / 32, BATCH), dim3(32, 8)>>>(x, xr, EDIM, TLEN);
    transpose_f2h<<<dim3(SLEN / 32, CDIM / 32, BATCH), dim3(32, 8)>>>(ctx, cr, CDIM, SLEN);

    // 1. weight standardization (all four, fp16 out)
    ws_kernel<<<dim3(EDIM, 4), 256>>>(qw, kw, vw, ow, wnq, wnkv, wno);

    // 2. merged Q + K + V projections: one launch, y-dispatch 8|8|8
    // Q: C[t,e] = sum_i xr[t,i] wnq[e,i]  -> q [B][T][E]; bias on n(e), mask on m(t)
    GP pQ = { xr, 1, (long)TLEN * EDIM, 0, EDIM,
              wnq, 1, 0, 0, EDIM,
              qbuf, 1, (long)TLEN * EDIM, 0, EDIM,
              EDIM, qb, 0, mask, 1, 1, TLEN, nullptr, 0, nullptr };
    // K: C[s,e] = sum_i cr[s,i] wnk[e,i]  -> k [B][S][E]; bias on n(e), mask on m(s)
    GP pK = { cr, 1, (long)SLEN * CDIM, 0, CDIM,
              wnk, 1, 0, 0, CDIM,
              kbuf, 1, (long)SLEN * EDIM, 0, EDIM,
              CDIM, kb, 0, mctx, 1, 1, SLEN, nullptr, 0, nullptr };
    // V: C[e,s] = sum_i wnv[e,i] cr[s,i]  -> v [B][E][S]; bias on m(e), mask on n(s)
    GP pV = { wnv, 1, 0, 0, CDIM,
              cr, 1, (long)SLEN * CDIM, 0, CDIM,
              vbuf, 1, (long)EDIM * SLEN, 0, SLEN,
              CDIM, vb, 1, mctx, 0, 1, SLEN, nullptr, 0, nullptr };
    mma_gemm<0, 128, 128, 3, 2><<<dim3(8, 24, BATCH), 128, SM_PROJ>>>(pQ, pK, pV, 8, 16);

    // 3. per-head LayerNorm over dh (q scaled by 1/256)
    ln_kernel<<<dim3(TLEN / 128, 3 * BATCH * NH), 128>>>(qbuf, kbuf, vbuf,
                                                         gq, bq, gk, bk, gv, bv);

    // 4. P[t,s] = mask[t] ? exp(sum_d q'[t,d] k[s,d]) : 0, + column partials -> rp
    GP pS = { qbuf, NH, (long)TLEN * EDIM, DH, EDIM,
              kbuf, NH, (long)SLEN * EDIM, DH, EDIM,
              pbuf, 1, (long)TLEN * SLEN, 0, SLEN,
              DH, nullptr, 0, mask, 1, NH, TLEN, nullptr, 0, rpbuf };
    mma_gemm<3, 128, 128, 3, 2><<<dim3(SLEN / 128, TLEN / 128, BATCH * NH), 128, SM_SC>>>(
        pS, pS, pS, 1 << 30, 1 << 30);

    // 5. finalize r; v' = v * r
    finalize_r<<<BATCH * NH * SLEN / 256, 256>>>(rpbuf, rbuf, mctx);
    vscale_kernel<<<BATCH * EDIM * SLEN / 4 / 256, 256>>>(vbuf, rbuf);

    // 6. att[t,d] = sum_s P[t,s] v'[d,s]  -> att [B][T][E] (head col slices)
    GP pA = { pbuf, 1, (long)TLEN * SLEN, 0, SLEN,
              vbuf, NH, (long)EDIM * SLEN, (long)DH * SLEN, SLEN,
              abuf, NH, (long)TLEN * EDIM, DH, EDIM,
              SLEN, nullptr, 0, mask, 1, 1, TLEN, nullptr, 0, nullptr };
    mma_gemm<2, 256, 64, 3, 2><<<dim3(1, TLEN / 256, BATCH * NH), 128, SM_AV>>>(
        pA, pA, pA, 1 << 30, 1 << 30);

    // 7. out[e,t] = sum_e' wno[e,e'] att[t,e'] + ob + mask + x
    GP pO = { wno, 1, 0, 0, EDIM,
              abuf, 1, (long)TLEN * EDIM, 0, EDIM,
              out, 1, (long)EDIM * TLEN, 0, TLEN,
              EDIM, ob, 1, mask, 0, 1, TLEN, x, (long)EDIM * TLEN, nullptr };
    mma_gemm<0, 128, 128, 3, 4><<<dim3(TLEN / 128, EDIM / 128, BATCH), 128, SM_OP>>>(
        pO, pO, pO, 1 << 30, 1 << 30);
}

// round 11
// speedup vs baseline: 1.8893x; 1.0511x over previous
#include <cuda_runtime.h>
#include <cuda_fp16.h>
#include <cstdint>

#define BATCH 4
#define EDIM 1024
#define CDIM 768
#define TLEN 1024
#define SLEN 1024
#define NH 16
#define DH 64
#define EPSV 1e-5f

// ---------------- scratch (static device globals; no allocation) ----------------
__device__ __half g_wnq[EDIM * EDIM];
__device__ __half g_wnkv[2 * EDIM * CDIM];              // [wnk ; wnv]
__device__ __half g_wno[EDIM * EDIM];
__device__ __half g_xr[BATCH * TLEN * EDIM];            // x^T  [B][T][E] fp16
__device__ __half g_cr[BATCH * SLEN * CDIM];            // ctx^T [B][S][C] fp16
__device__ __half g_q[BATCH * TLEN * EDIM];             // q [B][T][E]
__device__ __half g_k[BATCH * SLEN * EDIM];             // k [B][S][E]
__device__ __half g_v[BATCH * EDIM * SLEN];             // v [B][E][S]
__device__ __half g_p[(long)BATCH * NH * TLEN * SLEN];  // P [b,h][t][s] fp16
__device__ float g_rp[BATCH * NH * SLEN * 8];           // per-t-tile column partials
__device__ float g_r[BATCH * NH * SLEN];                // 1/rowsum (or 0)
__device__ __half g_att[BATCH * TLEN * EDIM];           // att [B][T][E]
__device__ unsigned char g_mask[BATCH * TLEN];
__device__ unsigned char g_mctx[BATCH * SLEN];

__device__ __forceinline__ uint32_t smem_u32(const void* p) {
    uint32_t a;
    asm("{ .reg .u64 t; cvta.to.shared.u64 t, %1; cvt.u32.u64 %0, t; }" : "=r"(a) : "l"(p));
    return a;
}
__device__ __forceinline__ uint32_t packh2(float lo, float hi) {
    __half2 h = __floats2half2_rn(lo, hi);
    return *(uint32_t*)&h;
}
#define CP16(dst, src) asm volatile("cp.async.cg.shared.global [%0], [%1], 16;" :: "r"(dst), "l"(src))
#define CPCOMMIT()     asm volatile("cp.async.commit_group;" ::: "memory")
#define CPWAIT(N)      asm volatile("cp.async.wait_group %0;" :: "n"(N) : "memory")

#define MMA_F16(d, a, b) \
    asm volatile("mma.sync.aligned.m16n8k16.row.col.f32.f16.f16.f32 " \
                 "{%0,%1,%2,%3}, {%4,%5,%6,%7}, {%8,%9}, {%0,%1,%2,%3};" \
                 : "+f"((d)[0]), "+f"((d)[1]), "+f"((d)[2]), "+f"((d)[3]) \
                 : "r"((a)[0]), "r"((a)[1]), "r"((a)[2]), "r"((a)[3]), \
                   "r"((b)[0]), "r"((b)[1]))

#define LDSM4(r0, r1, r2, r3, addr) \
    asm volatile("ldmatrix.sync.aligned.m8n8.x4.shared.b16 {%0,%1,%2,%3}, [%4];" \
                 : "=r"(r0), "=r"(r1), "=r"(r2), "=r"(r3) : "r"(addr))

// ---------------- GEMM parameter set ----------------
struct GP {
    const void* A; int aDiv; long aStrZa, aStrZb; int lda;
    const void* B; int bDiv; long bStrZa, bStrZb; int ldb;
    void* C; int cDiv; long cStrZa, cStrZb; int ldc;
    int K;
    const float* bias; int biasOnM;
    const unsigned char* mask; int maskOnM; int maskDiv; int maskLd;
    const float* res; long resStride;
    float* rp;                       // EPI==3 only: column-partial buffer
};

// ================= fp16 mma GEMM body: ALL operands [rows][k] k-contiguous =========
// C[m,n] = sum_k A[m,k] * B[n,k]   (fp16 operands, fp32 accum)
// smem: A [m][k] stride 40, B [n][k] stride 40; fragments via ldmatrix.x4.
// EPI 0: conv (bias on m or n; mask->0 on m or n; + residual when CBYTES==4)
// EPI 2: plain fp16 store
// EPI 3: exp-scores (c = mask[m] ? h(expf(c)) : 0) + per-COLUMN partial sums -> rp
template <int EPI, int BM, int BN, int NS, int CBYTES>
__device__ __forceinline__ void gemm_body(const GP& P, int ytile) {
    constexpr int AFL = BM * 40;
    constexpr int BFL = BN * 40;
    constexpr int STG = AFL + BFL;          // halves per stage
    constexpr int NWM = BM / 64;
    constexpr int MF = 4;
    constexpr int NF = 8;

    extern __shared__ char smch[];
    uint32_t sbase = smem_u32(smch);
    int tid = threadIdx.x, wid = tid >> 5, lane = tid & 31;
    int z = blockIdx.z;
    const __half* A = (const __half*)P.A + (z / P.aDiv) * P.aStrZa + (z % P.aDiv) * P.aStrZb;
    const __half* B = (const __half*)P.B + (z / P.bDiv) * P.bStrZa + (z % P.bDiv) * P.bStrZb;
    long mBase = (long)ytile * BM, nBase = (long)blockIdx.x * BN;
    int lda = P.lda, ldb = P.ldb, ldc = P.ldc;

    float acc[MF][NF][4];
#pragma unroll
    for (int i = 0; i < MF; ++i)
#pragma unroll
        for (int j = 0; j < NF; ++j)
#pragma unroll
            for (int t = 0; t < 4; ++t) acc[i][j][t] = 0.f;

    int nIter = P.K / 32;

    auto issue = [&](int stage, int k0) {
        uint32_t aoff = sbase + stage * STG * 2;
#pragma unroll
        for (int r = 0; r < BM / 32; ++r) {
            int lin = tid + 128 * r;
            int m = lin >> 2, kc = (lin & 3) * 8;
            CP16(aoff + (m * 40 + kc) * 2, &A[(mBase + m) * (long)lda + k0 + kc]);
        }
        uint32_t boff = sbase + (stage * STG + AFL) * 2;
#pragma unroll
        for (int r = 0; r < BN / 32; ++r) {
            int lin = tid + 128 * r;
            int n = lin >> 2, kc = (lin & 3) * 8;
            CP16(boff + (n * 40 + kc) * 2, &B[(nBase + n) * (long)ldb + k0 + kc]);
        }
    };

    int warpM = wid % NWM, warpN = wid / NWM;
    int mW = warpM * 64, nW = warpN * 64;
    int c4 = lane & 3, r4 = lane >> 2;
    int quad = lane >> 3, lrow = lane & 7;

    // ldmatrix role-based per-thread half-offsets (within a stage)
    //   A reg i <- lanes 8i..: row_off=(i&1)*8, col_off=(i>>1)*8  (a0..a3 mma order)
    //   B reg i <- lanes 8i..: row_off=(i>>1)*8, col_off=(i&1)*8  (b[2p][0],b[2p][1],b[2p+1][0],b[2p+1][1])
    uint32_t aRole[MF], bRole[NF / 2];
#pragma unroll
    for (int mf = 0; mf < MF; ++mf)
        aRole[mf] = (uint32_t)((mW + 16 * mf + (quad & 1) * 8 + lrow) * 40 + (quad >> 1) * 8);
#pragma unroll
    for (int p = 0; p < NF / 2; ++p)
        bRole[p] = (uint32_t)((nW + 16 * p + (quad >> 1) * 8 + lrow) * 40 + (quad & 1) * 8);

    auto compute = [&](int stage) {
        uint32_t As_b = sbase + stage * STG * 2;
        uint32_t Bs_b = As_b + AFL * 2;
#pragma unroll
        for (int kk = 0; kk < 32; kk += 16) {
            uint32_t a[MF][4];
#pragma unroll
            for (int mf = 0; mf < MF; ++mf)
                LDSM4(a[mf][0], a[mf][1], a[mf][2], a[mf][3], As_b + (aRole[mf] + kk) * 2);
            uint32_t b[NF][2];
#pragma unroll
            for (int p = 0; p < NF / 2; ++p)
                LDSM4(b[2 * p][0], b[2 * p][1], b[2 * p + 1][0], b[2 * p + 1][1],
                      Bs_b + (bRole[p] + kk) * 2);
#pragma unroll
            for (int mf = 0; mf < MF; ++mf)
#pragma unroll
                for (int nf = 0; nf < NF; ++nf)
                    MMA_F16(acc[mf][nf], a[mf], b[nf]);
        }
    };

    for (int s = 0; s < NS - 1; ++s) {
        if (s < nIter) issue(s, s * 32);
        CPCOMMIT();
    }
    for (int it = 0; it < nIter; ++it) {
        CPWAIT(NS - 2);
        __syncthreads();
        compute(it % NS);
        __syncthreads();
        int nx = it + NS - 1;
        if (nx < nIter) issue(nx % NS, nx * 32);
        CPCOMMIT();
    }

    // ---- epilogue ----
    int mb = z / P.maskDiv;
    float bn[NF][2];
    unsigned char mn[NF][2];
    if (EPI == 0) {
#pragma unroll
        for (int nf = 0; nf < NF; ++nf) {
            long n = nBase + nW + nf * 8 + 2 * c4;
            bn[nf][0] = P.biasOnM ? 0.f : P.bias[n];
            bn[nf][1] = P.biasOnM ? 0.f : P.bias[n + 1];
            mn[nf][0] = P.maskOnM ? 1 : P.mask[(long)mb * P.maskLd + n];
            mn[nf][1] = P.maskOnM ? 1 : P.mask[(long)mb * P.maskLd + n + 1];
        }
    }
    float rsumN[NF * 2];
#pragma unroll
    for (int q = 0; q < NF * 2; ++q) rsumN[q] = 0.f;

#pragma unroll
    for (int mf = 0; mf < MF; ++mf) {
#pragma unroll
        for (int half = 0; half < 2; ++half) {
            long m = mBase + mW + mf * 16 + r4 + half * 8;
            float bvm = (EPI == 0 && P.biasOnM) ? P.bias[m] : 0.f;
            bool mOK = true;
            if ((EPI == 0 || EPI == 3) && P.maskOnM)
                mOK = P.mask[(long)mb * P.maskLd + m] != 0;
#pragma unroll
            for (int nf = 0; nf < NF; ++nf) {
                long n = nBase + nW + nf * 8 + 2 * c4;
                float v0 = acc[mf][nf][half * 2 + 0];
                float v1 = acc[mf][nf][half * 2 + 1];
                if (EPI == 0) {
                    if (P.biasOnM) { v0 += bvm; v1 += bvm; }
                    else { v0 += bn[nf][0]; v1 += bn[nf][1]; }
                    if (P.maskOnM) { if (!mOK) { v0 = 0.f; v1 = 0.f; } }
                    else { if (!mn[nf][0]) v0 = 0.f; if (!mn[nf][1]) v1 = 0.f; }
                } else if (EPI == 3) {
                    __half h0 = __float2half_rn(__expf(v0));
                    __half h1 = __float2half_rn(__expf(v1));
                    v0 = mOK ? __half2float(h0) : 0.f;
                    v1 = mOK ? __half2float(h1) : 0.f;
                    rsumN[nf * 2 + 0] += v0;
                    rsumN[nf * 2 + 1] += v1;
                }
                if (CBYTES == 4) {
                    float* Cf = (float*)P.C + (z / P.cDiv) * P.cStrZa + (z % P.cDiv) * P.cStrZb;
                    if (EPI == 0 && P.res) {
                        v0 += P.res[z * P.resStride + m * ldc + n];
                        v1 += P.res[z * P.resStride + m * ldc + n + 1];
                    }
                    float2 o; o.x = v0; o.y = v1;
                    *(float2*)&Cf[m * ldc + n] = o;
                } else {
                    __half* Ch = (__half*)P.C + (z / P.cDiv) * P.cStrZa + (z % P.cDiv) * P.cStrZb;
                    *(uint32_t*)&Ch[m * ldc + n] = packh2(v0, v1);
                }
            }
        }
    }
    if (EPI == 3) {
        // column sums: reduce over r4 lanes (rows), then across warpM warps via smem
#pragma unroll
        for (int q = 0; q < NF * 2; ++q) {
            float v = rsumN[q];
            v += __shfl_xor_sync(0xFFFFFFFFu, v, 4);
            v += __shfl_xor_sync(0xFFFFFFFFu, v, 8);
            v += __shfl_xor_sync(0xFFFFFFFFu, v, 16);
            rsumN[q] = v;
        }
        __syncthreads();
        float* red = (float*)smch;           // [NWM][BN]
        if (r4 == 0) {
#pragma unroll
            for (int nf = 0; nf < NF; ++nf) {
                int nl = nW + nf * 8 + 2 * c4;
                red[warpM * BN + nl] = rsumN[nf * 2 + 0];
                red[warpM * BN + nl + 1] = rsumN[nf * 2 + 1];
            }
        }
        __syncthreads();
        if (tid < BN) {
            float s = red[tid];
#pragma unroll
            for (int w = 1; w < NWM; ++w) s += red[w * BN + tid];
            P.rp[((long)z * SLEN + nBase + tid) * 8 + ytile] = s;
        }
    }
}

// kernel wrapper with uniform triple-param-set dispatch on blockIdx.y
template <int EPI, int BM, int BN, int NS, int CBYTES>
__global__ __launch_bounds__(128) void mma_gemm(GP p0, GP p1, GP p2, int y1, int y2) {
    int y = blockIdx.y;
    if (y < y1) gemm_body<EPI, BM, BN, NS, CBYTES>(p0, y);
    else if (y < y2) gemm_body<EPI, BM, BN, NS, CBYTES>(p1, y - y1);
    else gemm_body<EPI, BM, BN, NS, CBYTES>(p2, y - y2);
}

// ---------------- mask canonicalization (bool-bytes or int32), both masks ----------------
__global__ void canon_mask_kernel(const unsigned char* __restrict__ raw0,
                                  const unsigned char* __restrict__ raw1,
                                  unsigned char* __restrict__ out0,
                                  unsigned char* __restrict__ out1, int n) {
    const unsigned char* raw = blockIdx.y ? raw1 : raw0;
    unsigned char* out = blockIdx.y ? out1 : out0;
    __shared__ int s_flag;
    if (threadIdx.x == 0) s_flag = 0;
    __syncthreads();
    int local = 0;
    for (int i = threadIdx.x; i < n; i += blockDim.x)
        if ((i & 3) != 0 && raw[i] != 0) local = 1;
    if (local) atomicOr(&s_flag, 1);
    __syncthreads();
    bool is_bool = (s_flag != 0);
    for (int i = threadIdx.x; i < n; i += blockDim.x)
        out[i] = is_bool ? raw[i] : raw[4 * i];
}

// ---------------- tiled transpose fp32 -> fp16: in [R][C] -> out [C][R] per batch ----------------
__global__ void transpose_f2h(const float* __restrict__ in, __half* __restrict__ out,
                              int R, int C) {
    __shared__ float tile[32][33];
    int b = blockIdx.z;
    const float* src = in + (long)b * R * C;
    __half* dst = out + (long)b * R * C;
    int c0 = blockIdx.x * 32, r0 = blockIdx.y * 32;
    int tx = threadIdx.x, ty = threadIdx.y;      // 32 x 8
#pragma unroll
    for (int i = 0; i < 32; i += 8)
        tile[ty + i][tx] = src[(long)(r0 + ty + i) * C + c0 + tx];
    __syncthreads();
#pragma unroll
    for (int i = 0; i < 32; i += 8)
        dst[(long)(c0 + ty + i) * R + r0 + tx] = __float2half_rn(tile[tx][ty + i]);
}

// ---------------- weight standardization, all 4 weights in one launch ----------------
__global__ void ws_kernel(const float* __restrict__ qw, const float* __restrict__ kw,
                          const float* __restrict__ vw, const float* __restrict__ ow,
                          __half* __restrict__ wnq, __half* __restrict__ wnkv,
                          __half* __restrict__ wno) {
    int c = blockIdx.y;
    const float* w; __half* outp; int I;
    if (c == 0) { w = qw; outp = wnq; I = EDIM; }
    else if (c == 1) { w = kw; outp = wnkv; I = CDIM; }
    else if (c == 2) { w = vw; outp = wnkv + EDIM * CDIM; I = CDIM; }
    else { w = ow; outp = wno; I = EDIM; }
    int o = blockIdx.x;
    const float* row = w + (long)o * I;
    float s = 0.f, ss = 0.f;
    for (int i = threadIdx.x; i < I; i += 256) {
        float v = row[i];
        s += v; ss += v * v;
    }
#pragma unroll
    for (int off = 16; off; off >>= 1) {
        s += __shfl_xor_sync(0xFFFFFFFFu, s, off);
        ss += __shfl_xor_sync(0xFFFFFFFFu, ss, off);
    }
    __shared__ float sh[16];
    int wid = threadIdx.x >> 5;
    if ((threadIdx.x & 31) == 0) { sh[wid] = s; sh[8 + wid] = ss; }
    __syncthreads();
    if (threadIdx.x == 0) {
        float ts = 0.f, tss = 0.f;
        for (int i = 0; i < 8; i++) { ts += sh[i]; tss += sh[8 + i]; }
        float mu = ts / (float)I;
        float var = tss / (float)I - mu * mu;
        sh[0] = mu; sh[1] = rsqrtf(var + EPSV);
    }
    __syncthreads();
    float mu = sh[0], inv = sh[1];
    for (int i = threadIdx.x; i < I; i += 256)
        outp[(long)o * I + i] = __float2half_rn((row[i] - mu) * inv);
}

// ---------------- per-head LayerNorm over dh=64 ----------------
// c=0: q [B][T][E] contiguous dh (scale 1/256); c=1: k [B][S][E]; c=2: v [B][E][S] strided
__global__ void ln_kernel(__half* __restrict__ qbuf, __half* __restrict__ kbuf,
                          __half* __restrict__ vbuf,
                          const float* __restrict__ gq, const float* __restrict__ bq,
                          const float* __restrict__ gk, const float* __restrict__ bk,
                          const float* __restrict__ gv, const float* __restrict__ bv) {
    int c = blockIdx.y / (BATCH * NH);
    int bh = blockIdx.y % (BATCH * NH);
    int b = bh / NH, h = bh % NH;
    int l = blockIdx.x * blockDim.x + threadIdx.x;
    float vals[DH];
    float s = 0.f, ss = 0.f;
    if (c < 2) {
        __half* base = (c == 0 ? qbuf : kbuf) + ((long)b * TLEN + l) * EDIM + h * DH;
        const float* g = c == 0 ? gq : gk;
        const float* bt = c == 0 ? bq : bk;
        float scale = c == 0 ? (1.f / 256.f) : 1.f;
#pragma unroll
        for (int i = 0; i < 8; ++i) {
            uint4 u = ((const uint4*)base)[i];
            const __half2* hp = (const __half2*)&u;
#pragma unroll
            for (int j = 0; j < 4; ++j) {
                float2 f = __half22float2(hp[j]);
                vals[i * 8 + j * 2] = f.x;
                vals[i * 8 + j * 2 + 1] = f.y;
                s += f.x + f.y;
                ss += f.x * f.x + f.y * f.y;
            }
        }
        float mu = s * (1.f / DH);
        float var = ss * (1.f / DH) - mu * mu;
        float inv = rsqrtf(var + EPSV);
#pragma unroll
        for (int i = 0; i < 8; ++i) {
            uint4 u;
            uint32_t* up = (uint32_t*)&u;
#pragma unroll
            for (int j = 0; j < 4; ++j) {
                int d0 = i * 8 + j * 2;
                up[j] = packh2(((vals[d0] - mu) * inv * g[d0] + bt[d0]) * scale,
                               ((vals[d0 + 1] - mu) * inv * g[d0 + 1] + bt[d0 + 1]) * scale);
            }
            ((uint4*)base)[i] = u;
        }
    } else {
        __half* base = vbuf + (long)b * EDIM * SLEN + (long)h * DH * SLEN + l;
#pragma unroll
        for (int d = 0; d < DH; d++) {
            float v = __half2float(base[(long)d * SLEN]);
            vals[d] = v;
            s += v; ss += v * v;
        }
        float mu = s * (1.f / DH);
        float var = ss * (1.f / DH) - mu * mu;
        float inv = rsqrtf(var + EPSV);
#pragma unroll
        for (int d = 0; d < DH; d++)
            base[(long)d * SLEN] = __float2half_rn((vals[d] - mu) * inv * gv[d] + bv[d]);
    }
}

// ---------------- finalize r: r[i] = mctx && sum>0 ? 1/sum(rp[i][0..7]) : 0 ----------------
__global__ void finalize_r(const float* __restrict__ rp, float* __restrict__ r,
                           const unsigned char* __restrict__ mctx) {
    int i = blockIdx.x * blockDim.x + threadIdx.x;     // 0..65535
    float4 a = ((const float4*)rp)[i * 2];
    float4 b = ((const float4*)rp)[i * 2 + 1];
    float s = ((a.x + a.y) + (a.z + a.w)) + ((b.x + b.y) + (b.z + b.w));
    int bidx = i >> 14, sidx = i & (SLEN - 1);
    r[i] = (mctx[bidx * SLEN + sidx] && s > 0.f) ? (1.f / s) : 0.f;
}

// ---------------- v' = h(v * r[b,h,s]) in-place (fp16) ----------------
__global__ void vscale_kernel(__half* __restrict__ vbuf, const float* __restrict__ r) {
    long i = (long)blockIdx.x * blockDim.x + threadIdx.x;   // 4-half groups over [B][E][S]
    long fi = i * 4;
    int b = (int)(fi / ((long)EDIM * SLEN));
    long rem = fi % ((long)EDIM * SLEN);
    int e = (int)(rem / SLEN), s = (int)(rem % SLEN);
    int h = e / DH;
    __half* vp = vbuf + (long)b * EDIM * SLEN + (long)e * SLEN + s;
    float4 rv = *(const float4*)&r[((long)b * NH + h) * SLEN + s];
    uint2 v = *(uint2*)vp;
    __half2 v01 = *(__half2*)&v.x, v23 = *(__half2*)&v.y;
    uint2 o;
    o.x = packh2(__half2float(v01.x) * rv.x, __half2float(v01.y) * rv.y);
    o.y = packh2(__half2float(v23.x) * rv.z, __half2float(v23.y) * rv.w);
    *(uint2*)vp = o;
}

// ---------------- launch ----------------
extern "C" void kernel_launch(void* const* d_in, const int* in_sizes, int n_in,
                              void* d_out, int out_size) {
    const float* x = (const float*)d_in[0];
    const float* ctx = (const float*)d_in[1];
    const unsigned char* mask_raw = (const unsigned char*)d_in[2];
    const unsigned char* mctx_raw = (const unsigned char*)d_in[3];
    const float* qw = (const float*)d_in[4];
    const float* qb = (const float*)d_in[5];
    const float* kw = (const float*)d_in[6];
    const float* kb = (const float*)d_in[7];
    const float* vw = (const float*)d_in[8];
    const float* vb = (const float*)d_in[9];
    const float* ow = (const float*)d_in[10];
    const float* ob = (const float*)d_in[11];
    const float* gq = (const float*)d_in[12];
    const float* bq = (const float*)d_in[13];
    const float* gk = (const float*)d_in[14];
    const float* bk = (const float*)d_in[15];
    const float* gv = (const float*)d_in[16];
    const float* bv = (const float*)d_in[17];
    float* out = (float*)d_out;

    __half *wnq, *wnkv, *wno, *xr, *cr, *qbuf, *kbuf, *vbuf, *pbuf, *abuf;
    float *rpbuf, *rbuf;
    unsigned char *mask, *mctx;
    cudaGetSymbolAddress((void**)&wnq, g_wnq);
    cudaGetSymbolAddress((void**)&wnkv, g_wnkv);
    cudaGetSymbolAddress((void**)&wno, g_wno);
    cudaGetSymbolAddress((void**)&xr, g_xr);
    cudaGetSymbolAddress((void**)&cr, g_cr);
    cudaGetSymbolAddress((void**)&qbuf, g_q);
    cudaGetSymbolAddress((void**)&kbuf, g_k);
    cudaGetSymbolAddress((void**)&vbuf, g_v);
    cudaGetSymbolAddress((void**)&pbuf, g_p);
    cudaGetSymbolAddress((void**)&rpbuf, g_rp);
    cudaGetSymbolAddress((void**)&rbuf, g_r);
    cudaGetSymbolAddress((void**)&abuf, g_att);
    cudaGetSymbolAddress((void**)&mask, g_mask);
    cudaGetSymbolAddress((void**)&mctx, g_mctx);

    __half* wnk = wnkv;
    __half* wnv = wnkv + EDIM * CDIM;

    const int SM_PROJ = 3 * (128 + 128) * 40 * 2;   // 61440
    const int SM_SC = 3 * (128 + 128) * 40 * 2;     // 61440
    const int SM_AV = 3 * (256 + 64) * 40 * 2;      // 76800
    const int SM_OP = 3 * (128 + 128) * 40 * 2;     // 61440
    cudaFuncSetAttribute((const void*)mma_gemm<0, 128, 128, 3, 2>,
                         cudaFuncAttributeMaxDynamicSharedMemorySize, SM_PROJ);
    cudaFuncSetAttribute((const void*)mma_gemm<3, 128, 128, 3, 2>,
                         cudaFuncAttributeMaxDynamicSharedMemorySize, SM_SC);
    cudaFuncSetAttribute((const void*)mma_gemm<2, 256, 64, 3, 2>,
                         cudaFuncAttributeMaxDynamicSharedMemorySize, SM_AV);
    cudaFuncSetAttribute((const void*)mma_gemm<0, 128, 128, 3, 4>,
                         cudaFuncAttributeMaxDynamicSharedMemorySize, SM_OP);

    // 0. canonicalize masks; transpose+round inputs to fp16
    canon_mask_kernel<<<dim3(1, 2), 256>>>(mask_raw, mctx_raw, mask, mctx, BATCH * TLEN);
    transpose_f2h<<<dim3(TLEN / 32, EDIM / 32, BATCH), dim3(32, 8)>>>(x, xr, EDIM, TLEN);
    transpose_f2h<<<dim3(SLEN / 32, CDIM / 32, BATCH), dim3(32, 8)>>>(ctx, cr, CDIM, SLEN);

    // 1. weight standardization (all four, fp16 out)
    ws_kernel<<<dim3(EDIM, 4), 256>>>(qw, kw, vw, ow, wnq, wnkv, wno);

    // 2. merged Q + K + V projections: one launch, y-dispatch 8|8|8
    GP pQ = { xr, 1, (long)TLEN * EDIM, 0, EDIM,
              wnq, 1, 0, 0, EDIM,
              qbuf, 1, (long)TLEN * EDIM, 0, EDIM,
              EDIM, qb, 0, mask, 1, 1, TLEN, nullptr, 0, nullptr };
    GP pK = { cr, 1, (long)SLEN * CDIM, 0, CDIM,
              wnk, 1, 0, 0, CDIM,
              kbuf, 1, (long)SLEN * EDIM, 0, EDIM,
              CDIM, kb, 0, mctx, 1, 1, SLEN, nullptr, 0, nullptr };
    GP pV = { wnv, 1, 0, 0, CDIM,
              cr, 1, (long)SLEN * CDIM, 0, CDIM,
              vbuf, 1, (long)EDIM * SLEN, 0, SLEN,
              CDIM, vb, 1, mctx, 0, 1, SLEN, nullptr, 0, nullptr };
    mma_gemm<0, 128, 128, 3, 2><<<dim3(8, 24, BATCH), 128, SM_PROJ>>>(pQ, pK, pV, 8, 16);

    // 3. per-head LayerNorm over dh (q scaled by 1/256)
    ln_kernel<<<dim3(TLEN / 128, 3 * BATCH * NH), 128>>>(qbuf, kbuf, vbuf,
                                                         gq, bq, gk, bk, gv, bv);

    // 4. P[t,s] = mask[t] ? exp(sum_d q'[t,d] k[s,d]) : 0, + column partials -> rp
    GP pS = { qbuf, NH, (long)TLEN * EDIM, DH, EDIM,
              kbuf, NH, (long)SLEN * EDIM, DH, EDIM,
              pbuf, 1, (long)TLEN * SLEN, 0, SLEN,
              DH, nullptr, 0, mask, 1, NH, TLEN, nullptr, 0, rpbuf };
    mma_gemm<3, 128, 128, 3, 2><<<dim3(SLEN / 128, TLEN / 128, BATCH * NH), 128, SM_SC>>>(
        pS, pS, pS, 1 << 30, 1 << 30);

    // 5. finalize r; v' = v * r
    finalize_r<<<BATCH * NH * SLEN / 256, 256>>>(rpbuf, rbuf, mctx);
    vscale_kernel<<<BATCH * EDIM * SLEN / 4 / 256, 256>>>(vbuf, rbuf);

    // 6. att[t,d] = sum_s P[t,s] v'[d,s]  -> att [B][T][E] (head col slices)
    GP pA = { pbuf, 1, (long)TLEN * SLEN, 0, SLEN,
              vbuf, NH, (long)EDIM * SLEN, (long)DH * SLEN, SLEN,
              abuf, NH, (long)TLEN * EDIM, DH, EDIM,
              SLEN, nullptr, 0, mask, 1, 1, TLEN, nullptr, 0, nullptr };
    mma_gemm<2, 256, 64, 3, 2><<<dim3(1, TLEN / 256, BATCH * NH), 128, SM_AV>>>(
        pA, pA, pA, 1 << 30, 1 << 30);

    // 7. out[e,t] = sum_e' wno[e,e'] att[t,e'] + ob + mask + x
    GP pO = { wno, 1, 0, 0, EDIM,
              abuf, 1, (long)TLEN * EDIM, 0, EDIM,
              out, 1, (long)EDIM * TLEN, 0, TLEN,
              EDIM, ob, 1, mask, 0, 1, TLEN, x, (long)EDIM * TLEN, nullptr };
    mma_gemm<0, 128, 128, 3, 4><<<dim3(TLEN / 128, EDIM / 128, BATCH), 128, SM_OP>>>(
        pO, pO, pO, 1 << 30, 1 << 30);
}

// round 12
// speedup vs baseline: 2.0870x; 1.1047x over previous
#include <cuda_runtime.h>
#include <cuda_fp16.h>
#include <cstdint>

#define BATCH 4
#define EDIM 1024
#define CDIM 768
#define TLEN 1024
#define SLEN 1024
#define NH 16
#define DH 64
#define EPSV 1e-5f

// ---------------- scratch (static device globals; no allocation) ----------------
__device__ __half g_wnq[EDIM * EDIM];
__device__ __half g_wnkv[2 * EDIM * CDIM];              // [wnk ; wnv]
__device__ __half g_wno[EDIM * EDIM];
__device__ __half g_xr[BATCH * TLEN * EDIM];            // x^T  [B][T][E] fp16
__device__ __half g_cr[BATCH * SLEN * CDIM];            // ctx^T [B][S][C] fp16
__device__ __half g_q[BATCH * TLEN * EDIM];             // q [B][T][E]
__device__ __half g_k[BATCH * SLEN * EDIM];             // k [B][S][E]
__device__ __half g_v[BATCH * EDIM * SLEN];             // v [B][E][S]
__device__ __half g_p[(long)BATCH * NH * TLEN * SLEN];  // P [b,h][t][s] fp16
__device__ float g_rp[BATCH * NH * SLEN * 8];           // per-t-tile column partials
__device__ float g_r[BATCH * NH * SLEN];                // 1/rowsum (or 0)
__device__ __half g_att[BATCH * TLEN * EDIM];           // att [B][T][E]
__device__ unsigned char g_mask[BATCH * TLEN];
__device__ unsigned char g_mctx[BATCH * SLEN];

__device__ __forceinline__ uint32_t smem_u32(const void* p) {
    uint32_t a;
    asm("{ .reg .u64 t; cvta.to.shared.u64 t, %1; cvt.u32.u64 %0, t; }" : "=r"(a) : "l"(p));
    return a;
}
__device__ __forceinline__ uint32_t packh2(float lo, float hi) {
    __half2 h = __floats2half2_rn(lo, hi);
    return *(uint32_t*)&h;
}
#define CP16(dst, src) asm volatile("cp.async.cg.shared.global [%0], [%1], 16;" :: "r"(dst), "l"(src))
#define CPCOMMIT()     asm volatile("cp.async.commit_group;" ::: "memory")
#define CPWAIT(N)      asm volatile("cp.async.wait_group %0;" :: "n"(N) : "memory")

#define MMA_F16(d, a, b) \
    asm volatile("mma.sync.aligned.m16n8k16.row.col.f32.f16.f16.f32 " \
                 "{%0,%1,%2,%3}, {%4,%5,%6,%7}, {%8,%9}, {%0,%1,%2,%3};" \
                 : "+f"((d)[0]), "+f"((d)[1]), "+f"((d)[2]), "+f"((d)[3]) \
                 : "r"((a)[0]), "r"((a)[1]), "r"((a)[2]), "r"((a)[3]), \
                   "r"((b)[0]), "r"((b)[1]))

#define LDSM4(r0, r1, r2, r3, addr) \
    asm volatile("ldmatrix.sync.aligned.m8n8.x4.shared.b16 {%0,%1,%2,%3}, [%4];" \
                 : "=r"(r0), "=r"(r1), "=r"(r2), "=r"(r3) : "r"(addr))

// ---------------- GEMM parameter set ----------------
struct GP {
    const void* A; int aDiv; long aStrZa, aStrZb; int lda;
    const void* B; int bDiv; long bStrZa, bStrZb; int ldb;
    void* C; int cDiv; long cStrZa, cStrZb; int ldc;
    int K;
    const float* bias; int biasOnM;
    const unsigned char* mask; int maskOnM; int maskDiv; int maskLd;
    const float* res; long resStride;
    float* rp;                       // EPI==3 only: column-partial buffer
};

// ================= fp16 mma GEMM body: BK=64, single-sync pipeline =================
// C[m,n] = sum_k A[m,k] * B[n,k]   (fp16 operands, fp32 accum)
// smem: A [m][k] stride 72, B [n][k] stride 72; fragments via ldmatrix.x4.
// EPI 0: conv (bias on m or n; mask->0 on m or n; + residual when CBYTES==4)
// EPI 2: plain fp16 store
// EPI 3: exp-scores (c = mask[m] ? h(expf(c)) : 0) + per-COLUMN partial sums -> rp
template <int EPI, int BM, int BN, int NS, int CBYTES>
__device__ __forceinline__ void gemm_body(const GP& P, int ytile) {
    constexpr int BK = 64;
    constexpr int STR = BK + 8;             // 72 halves per row
    constexpr int AFL = BM * STR;
    constexpr int BFL = BN * STR;
    constexpr int STG = AFL + BFL;          // halves per stage
    constexpr int NWM = BM / 64;
    constexpr int MF = 4;
    constexpr int NF = 8;

    extern __shared__ char smch[];
    uint32_t sbase = smem_u32(smch);
    int tid = threadIdx.x, wid = tid >> 5, lane = tid & 31;
    int z = blockIdx.z;
    const __half* A = (const __half*)P.A + (z / P.aDiv) * P.aStrZa + (z % P.aDiv) * P.aStrZb;
    const __half* B = (const __half*)P.B + (z / P.bDiv) * P.bStrZa + (z % P.bDiv) * P.bStrZb;
    long mBase = (long)ytile * BM, nBase = (long)blockIdx.x * BN;
    int lda = P.lda, ldb = P.ldb, ldc = P.ldc;

    float acc[MF][NF][4];
#pragma unroll
    for (int i = 0; i < MF; ++i)
#pragma unroll
        for (int j = 0; j < NF; ++j)
#pragma unroll
            for (int t = 0; t < 4; ++t) acc[i][j][t] = 0.f;

    int nIter = P.K / BK;

    auto issue = [&](int stage, int k0) {
        uint32_t aoff = sbase + stage * STG * 2;
#pragma unroll
        for (int r = 0; r < BM / 16; ++r) {       // BM rows x 8 chunks / 128 thr
            int lin = tid + 128 * r;
            int m = lin >> 3, kc = (lin & 7) * 8;
            CP16(aoff + (m * STR + kc) * 2, &A[(mBase + m) * (long)lda + k0 + kc]);
        }
        uint32_t boff = sbase + (stage * STG + AFL) * 2;
#pragma unroll
        for (int r = 0; r < BN / 16; ++r) {
            int lin = tid + 128 * r;
            int n = lin >> 3, kc = (lin & 7) * 8;
            CP16(boff + (n * STR + kc) * 2, &B[(nBase + n) * (long)ldb + k0 + kc]);
        }
    };

    int warpM = wid % NWM, warpN = wid / NWM;
    int mW = warpM * 64, nW = warpN * 64;
    int c4 = lane & 3, r4 = lane >> 2;
    int quad = lane >> 3, lrow = lane & 7;

    // ldmatrix role-based per-thread half-offsets (within a stage)
    uint32_t aRole[MF], bRole[NF / 2];
#pragma unroll
    for (int mf = 0; mf < MF; ++mf)
        aRole[mf] = (uint32_t)((mW + 16 * mf + (quad & 1) * 8 + lrow) * STR + (quad >> 1) * 8);
#pragma unroll
    for (int p = 0; p < NF / 2; ++p)
        bRole[p] = (uint32_t)((nW + 16 * p + (quad >> 1) * 8 + lrow) * STR + (quad & 1) * 8);

    auto compute = [&](int stage) {
        uint32_t As_b = sbase + stage * STG * 2;
        uint32_t Bs_b = As_b + AFL * 2;
#pragma unroll
        for (int kk = 0; kk < BK; kk += 16) {
            uint32_t a[MF][4];
#pragma unroll
            for (int mf = 0; mf < MF; ++mf)
                LDSM4(a[mf][0], a[mf][1], a[mf][2], a[mf][3], As_b + (aRole[mf] + kk) * 2);
            uint32_t b[NF][2];
#pragma unroll
            for (int p = 0; p < NF / 2; ++p)
                LDSM4(b[2 * p][0], b[2 * p][1], b[2 * p + 1][0], b[2 * p + 1][1],
                      Bs_b + (bRole[p] + kk) * 2);
#pragma unroll
            for (int mf = 0; mf < MF; ++mf)
#pragma unroll
                for (int nf = 0; nf < NF; ++nf)
                    MMA_F16(acc[mf][nf], a[mf], b[nf]);
        }
    };

    for (int s = 0; s < NS - 1; ++s) {
        if (s < nIter) issue(s, s * BK);
        CPCOMMIT();
    }
    // single-sync mainloop: top sync of iter it+1 proves all threads finished
    // compute(it) before anyone overwrites stage it%NS (issue at iter it+1).
    for (int it = 0; it < nIter; ++it) {
        CPWAIT(NS - 2);
        __syncthreads();
        compute(it % NS);
        int nx = it + NS - 1;
        if (nx < nIter) issue(nx % NS, nx * BK);
        CPCOMMIT();
    }

    // ---- epilogue ----
    int mb = z / P.maskDiv;
    float bn[NF][2];
    unsigned char mn[NF][2];
    if (EPI == 0) {
#pragma unroll
        for (int nf = 0; nf < NF; ++nf) {
            long n = nBase + nW + nf * 8 + 2 * c4;
            bn[nf][0] = P.biasOnM ? 0.f : P.bias[n];
            bn[nf][1] = P.biasOnM ? 0.f : P.bias[n + 1];
            mn[nf][0] = P.maskOnM ? 1 : P.mask[(long)mb * P.maskLd + n];
            mn[nf][1] = P.maskOnM ? 1 : P.mask[(long)mb * P.maskLd + n + 1];
        }
    }
    float rsumN[NF * 2];
#pragma unroll
    for (int q = 0; q < NF * 2; ++q) rsumN[q] = 0.f;

#pragma unroll
    for (int mf = 0; mf < MF; ++mf) {
#pragma unroll
        for (int half = 0; half < 2; ++half) {
            long m = mBase + mW + mf * 16 + r4 + half * 8;
            float bvm = (EPI == 0 && P.biasOnM) ? P.bias[m] : 0.f;
            bool mOK = true;
            if ((EPI == 0 || EPI == 3) && P.maskOnM)
                mOK = P.mask[(long)mb * P.maskLd + m] != 0;
#pragma unroll
            for (int nf = 0; nf < NF; ++nf) {
                long n = nBase + nW + nf * 8 + 2 * c4;
                float v0 = acc[mf][nf][half * 2 + 0];
                float v1 = acc[mf][nf][half * 2 + 1];
                if (EPI == 0) {
                    if (P.biasOnM) { v0 += bvm; v1 += bvm; }
                    else { v0 += bn[nf][0]; v1 += bn[nf][1]; }
                    if (P.maskOnM) { if (!mOK) { v0 = 0.f; v1 = 0.f; } }
                    else { if (!mn[nf][0]) v0 = 0.f; if (!mn[nf][1]) v1 = 0.f; }
                } else if (EPI == 3) {
                    __half h0 = __float2half_rn(__expf(v0));
                    __half h1 = __float2half_rn(__expf(v1));
                    v0 = mOK ? __half2float(h0) : 0.f;
                    v1 = mOK ? __half2float(h1) : 0.f;
                    rsumN[nf * 2 + 0] += v0;
                    rsumN[nf * 2 + 1] += v1;
                }
                if (CBYTES == 4) {
                    float* Cf = (float*)P.C + (z / P.cDiv) * P.cStrZa + (z % P.cDiv) * P.cStrZb;
                    if (EPI == 0 && P.res) {
                        v0 += P.res[z * P.resStride + m * ldc + n];
                        v1 += P.res[z * P.resStride + m * ldc + n + 1];
                    }
                    float2 o; o.x = v0; o.y = v1;
                    *(float2*)&Cf[m * ldc + n] = o;
                } else {
                    __half* Ch = (__half*)P.C + (z / P.cDiv) * P.cStrZa + (z % P.cDiv) * P.cStrZb;
                    *(uint32_t*)&Ch[m * ldc + n] = packh2(v0, v1);
                }
            }
        }
    }
    if (EPI == 3) {
        // column sums: reduce over r4 lanes (rows), then across warpM warps via smem
#pragma unroll
        for (int q = 0; q < NF * 2; ++q) {
            float v = rsumN[q];
            v += __shfl_xor_sync(0xFFFFFFFFu, v, 4);
            v += __shfl_xor_sync(0xFFFFFFFFu, v, 8);
            v += __shfl_xor_sync(0xFFFFFFFFu, v, 16);
            rsumN[q] = v;
        }
        __syncthreads();
        float* red = (float*)smch;           // [NWM][BN]
        if (r4 == 0) {
#pragma unroll
            for (int nf = 0; nf < NF; ++nf) {
                int nl = nW + nf * 8 + 2 * c4;
                red[warpM * BN + nl] = rsumN[nf * 2 + 0];
                red[warpM * BN + nl + 1] = rsumN[nf * 2 + 1];
            }
        }
        __syncthreads();
        if (tid < BN) {
            float s = red[tid];
#pragma unroll
            for (int w = 1; w < NWM; ++w) s += red[w * BN + tid];
            P.rp[((long)z * SLEN + nBase + tid) * 8 + ytile] = s;
        }
    }
}

// kernel wrapper with uniform triple-param-set dispatch on blockIdx.y
template <int EPI, int BM, int BN, int NS, int CBYTES>
__global__ __launch_bounds__(128) void mma_gemm(GP p0, GP p1, GP p2, int y1, int y2) {
    int y = blockIdx.y;
    if (y < y1) gemm_body<EPI, BM, BN, NS, CBYTES>(p0, y);
    else if (y < y2) gemm_body<EPI, BM, BN, NS, CBYTES>(p1, y - y1);
    else gemm_body<EPI, BM, BN, NS, CBYTES>(p2, y - y2);
}

// ================= preamble megakernel: canon + transpose x + transpose ctx + ws ======
__device__ void canon_body(const unsigned char* __restrict__ raw,
                           unsigned char* __restrict__ out, int n, int* flag) {
    if (threadIdx.x == 0) *flag = 0;
    __syncthreads();
    int local = 0;
    for (int i = threadIdx.x; i < n; i += 256)
        if ((i & 3) != 0 && raw[i] != 0) local = 1;
    if (local) atomicOr(flag, 1);
    __syncthreads();
    bool is_bool = (*flag != 0);
    for (int i = threadIdx.x; i < n; i += 256)
        out[i] = is_bool ? raw[i] : raw[4 * i];
}

__device__ void transpose_body(const float* __restrict__ in, __half* __restrict__ out,
                               int R, int C, int idx, float* tile /* 32x33 */) {
    int nxb = C / 32;
    int per = nxb * (R / 32);
    int b = idx / per;
    int rem = idx % per;
    int by = rem / nxb, bx = rem % nxb;
    const float* src = in + (long)b * R * C;
    __half* dst = out + (long)b * R * C;
    int c0 = bx * 32, r0 = by * 32;
    int tx = threadIdx.x & 31, ty = threadIdx.x >> 5;   // 32 x 8
#pragma unroll
    for (int i = 0; i < 32; i += 8)
        tile[(ty + i) * 33 + tx] = src[(long)(r0 + ty + i) * C + c0 + tx];
    __syncthreads();
#pragma unroll
    for (int i = 0; i < 32; i += 8)
        dst[(long)(c0 + ty + i) * R + r0 + tx] = __float2half_rn(tile[tx * 33 + ty + i]);
}

__device__ void ws_body(const float* __restrict__ w, __half* __restrict__ outp,
                        int I, int o, float* sh /* >=16 floats */) {
    const float* row = w + (long)o * I;
    float s = 0.f, ss = 0.f;
    for (int i = threadIdx.x; i < I; i += 256) {
        float v = row[i];
        s += v; ss += v * v;
    }
#pragma unroll
    for (int off = 16; off; off >>= 1) {
        s += __shfl_xor_sync(0xFFFFFFFFu, s, off);
        ss += __shfl_xor_sync(0xFFFFFFFFu, ss, off);
    }
    int wid = threadIdx.x >> 5;
    if ((threadIdx.x & 31) == 0) { sh[wid] = s; sh[8 + wid] = ss; }
    __syncthreads();
    if (threadIdx.x == 0) {
        float ts = 0.f, tss = 0.f;
        for (int i = 0; i < 8; i++) { ts += sh[i]; tss += sh[8 + i]; }
        float mu = ts / (float)I;
        float var = tss / (float)I - mu * mu;
        sh[0] = mu; sh[1] = rsqrtf(var + EPSV);
    }
    __syncthreads();
    float mu = sh[0], inv = sh[1];
    for (int i = threadIdx.x; i < I; i += 256)
        outp[(long)o * I + i] = __float2half_rn((row[i] - mu) * inv);
}

#define NB_TX (32 * 32 * BATCH)     // 4096
#define NB_TC (32 * 24 * BATCH)     // 3072
__global__ __launch_bounds__(256) void preamble_kernel(
    const float* __restrict__ x, const float* __restrict__ ctx,
    const unsigned char* __restrict__ mask_raw, const unsigned char* __restrict__ mctx_raw,
    const float* __restrict__ qw, const float* __restrict__ kw,
    const float* __restrict__ vw, const float* __restrict__ ow,
    __half* __restrict__ xr, __half* __restrict__ cr,
    unsigned char* __restrict__ mask, unsigned char* __restrict__ mctx,
    __half* __restrict__ wnq, __half* __restrict__ wnkv, __half* __restrict__ wno)
{
    __shared__ float shm[32 * 33];
    int b = blockIdx.x;
    if (b < 2) {
        canon_body(b ? mctx_raw : mask_raw, b ? mctx : mask, BATCH * TLEN, (int*)shm);
    } else if (b < 2 + NB_TX) {
        transpose_body(x, xr, EDIM, TLEN, b - 2, shm);
    } else if (b < 2 + NB_TX + NB_TC) {
        transpose_body(ctx, cr, CDIM, SLEN, b - 2 - NB_TX, shm);
    } else {
        int idx = b - 2 - NB_TX - NB_TC;
        int c = idx >> 10, o = idx & 1023;
        const float* w; __half* outp; int I;
        if (c == 0) { w = qw; outp = wnq; I = EDIM; }
        else if (c == 1) { w = kw; outp = wnkv; I = CDIM; }
        else if (c == 2) { w = vw; outp = wnkv + EDIM * CDIM; I = CDIM; }
        else { w = ow; outp = wno; I = EDIM; }
        ws_body(w, outp, I, o, shm);
    }
}

// ---------------- per-head LayerNorm over dh=64 ----------------
// c=0: q [B][T][E] contiguous dh (scale 1/256); c=1: k [B][S][E]; c=2: v [B][E][S] strided
__global__ void ln_kernel(__half* __restrict__ qbuf, __half* __restrict__ kbuf,
                          __half* __restrict__ vbuf,
                          const float* __restrict__ gq, const float* __restrict__ bq,
                          const float* __restrict__ gk, const float* __restrict__ bk,
                          const float* __restrict__ gv, const float* __restrict__ bv) {
    int c = blockIdx.y / (BATCH * NH);
    int bh = blockIdx.y % (BATCH * NH);
    int b = bh / NH, h = bh % NH;
    int l = blockIdx.x * blockDim.x + threadIdx.x;
    float vals[DH];
    float s = 0.f, ss = 0.f;
    if (c < 2) {
        __half* base = (c == 0 ? qbuf : kbuf) + ((long)b * TLEN + l) * EDIM + h * DH;
        const float* g = c == 0 ? gq : gk;
        const float* bt = c == 0 ? bq : bk;
        float scale = c == 0 ? (1.f / 256.f) : 1.f;
#pragma unroll
        for (int i = 0; i < 8; ++i) {
            uint4 u = ((const uint4*)base)[i];
            const __half2* hp = (const __half2*)&u;
#pragma unroll
            for (int j = 0; j < 4; ++j) {
                float2 f = __half22float2(hp[j]);
                vals[i * 8 + j * 2] = f.x;
                vals[i * 8 + j * 2 + 1] = f.y;
                s += f.x + f.y;
                ss += f.x * f.x + f.y * f.y;
            }
        }
        float mu = s * (1.f / DH);
        float var = ss * (1.f / DH) - mu * mu;
        float inv = rsqrtf(var + EPSV);
#pragma unroll
        for (int i = 0; i < 8; ++i) {
            uint4 u;
            uint32_t* up = (uint32_t*)&u;
#pragma unroll
            for (int j = 0; j < 4; ++j) {
                int d0 = i * 8 + j * 2;
                up[j] = packh2(((vals[d0] - mu) * inv * g[d0] + bt[d0]) * scale,
                               ((vals[d0 + 1] - mu) * inv * g[d0 + 1] + bt[d0 + 1]) * scale);
            }
            ((uint4*)base)[i] = u;
        }
    } else {
        __half* base = vbuf + (long)b * EDIM * SLEN + (long)h * DH * SLEN + l;
#pragma unroll
        for (int d = 0; d < DH; d++) {
            float v = __half2float(base[(long)d * SLEN]);
            vals[d] = v;
            s += v; ss += v * v;
        }
        float mu = s * (1.f / DH);
        float var = ss * (1.f / DH) - mu * mu;
        float inv = rsqrtf(var + EPSV);
#pragma unroll
        for (int d = 0; d < DH; d++)
            base[(long)d * SLEN] = __float2half_rn((vals[d] - mu) * inv * gv[d] + bv[d]);
    }
}

// ---------------- finalize r: r[i] = mctx && sum>0 ? 1/sum(rp[i][0..7]) : 0 ----------------
__global__ void finalize_r(const float* __restrict__ rp, float* __restrict__ r,
                           const unsigned char* __restrict__ mctx) {
    int i = blockIdx.x * blockDim.x + threadIdx.x;     // 0..65535
    float4 a = ((const float4*)rp)[i * 2];
    float4 b = ((const float4*)rp)[i * 2 + 1];
    float s = ((a.x + a.y) + (a.z + a.w)) + ((b.x + b.y) + (b.z + b.w));
    int bidx = i >> 14, sidx = i & (SLEN - 1);
    r[i] = (mctx[bidx * SLEN + sidx] && s > 0.f) ? (1.f / s) : 0.f;
}

// ---------------- v' = h(v * r[b,h,s]) in-place (fp16) ----------------
__global__ void vscale_kernel(__half* __restrict__ vbuf, const float* __restrict__ r) {
    long i = (long)blockIdx.x * blockDim.x + threadIdx.x;   // 4-half groups over [B][E][S]
    long fi = i * 4;
    int b = (int)(fi / ((long)EDIM * SLEN));
    long rem = fi % ((long)EDIM * SLEN);
    int e = (int)(rem / SLEN), s = (int)(rem % SLEN);
    int h = e / DH;
    __half* vp = vbuf + (long)b * EDIM * SLEN + (long)e * SLEN + s;
    float4 rv = *(const float4*)&r[((long)b * NH + h) * SLEN + s];
    uint2 v = *(uint2*)vp;
    __half2 v01 = *(__half2*)&v.x, v23 = *(__half2*)&v.y;
    uint2 o;
    o.x = packh2(__half2float(v01.x) * rv.x, __half2float(v01.y) * rv.y);
    o.y = packh2(__half2float(v23.x) * rv.z, __half2float(v23.y) * rv.w);
    *(uint2*)vp = o;
}

// ---------------- launch ----------------
extern "C" void kernel_launch(void* const* d_in, const int* in_sizes, int n_in,
                              void* d_out, int out_size) {
    const float* x = (const float*)d_in[0];
    const float* ctx = (const float*)d_in[1];
    const unsigned char* mask_raw = (const unsigned char*)d_in[2];
    const unsigned char* mctx_raw = (const unsigned char*)d_in[3];
    const float* qw = (const float*)d_in[4];
    const float* qb = (const float*)d_in[5];
    const float* kw = (const float*)d_in[6];
    const float* kb = (const float*)d_in[7];
    const float* vw = (const float*)d_in[8];
    const float* vb = (const float*)d_in[9];
    const float* ow = (const float*)d_in[10];
    const float* ob = (const float*)d_in[11];
    const float* gq = (const float*)d_in[12];
    const float* bq = (const float*)d_in[13];
    const float* gk = (const float*)d_in[14];
    const float* bk = (const float*)d_in[15];
    const float* gv = (const float*)d_in[16];
    const float* bv = (const float*)d_in[17];
    float* out = (float*)d_out;

    __half *wnq, *wnkv, *wno, *xr, *cr, *qbuf, *kbuf, *vbuf, *pbuf, *abuf;
    float *rpbuf, *rbuf;
    unsigned char *mask, *mctx;
    cudaGetSymbolAddress((void**)&wnq, g_wnq);
    cudaGetSymbolAddress((void**)&wnkv, g_wnkv);
    cudaGetSymbolAddress((void**)&wno, g_wno);
    cudaGetSymbolAddress((void**)&xr, g_xr);
    cudaGetSymbolAddress((void**)&cr, g_cr);
    cudaGetSymbolAddress((void**)&qbuf, g_q);
    cudaGetSymbolAddress((void**)&kbuf, g_k);
    cudaGetSymbolAddress((void**)&vbuf, g_v);
    cudaGetSymbolAddress((void**)&pbuf, g_p);
    cudaGetSymbolAddress((void**)&rpbuf, g_rp);
    cudaGetSymbolAddress((void**)&rbuf, g_r);
    cudaGetSymbolAddress((void**)&abuf, g_att);
    cudaGetSymbolAddress((void**)&mask, g_mask);
    cudaGetSymbolAddress((void**)&mctx, g_mctx);

    __half* wnk = wnkv;
    __half* wnv = wnkv + EDIM * CDIM;

    const int SM_PROJ = 3 * (128 + 128) * 72 * 2;   // 110592, NS=3
    const int SM_SC = 2 * (128 + 128) * 72 * 2;     // 73728,  NS=2
    const int SM_AV = 2 * (256 + 64) * 72 * 2;      // 92160,  NS=2
    const int SM_OP = 3 * (128 + 128) * 72 * 2;     // 110592, NS=3
    cudaFuncSetAttribute((const void*)mma_gemm<0, 128, 128, 3, 2>,
                         cudaFuncAttributeMaxDynamicSharedMemorySize, SM_PROJ);
    cudaFuncSetAttribute((const void*)mma_gemm<3, 128, 128, 2, 2>,
                         cudaFuncAttributeMaxDynamicSharedMemorySize, SM_SC);
    cudaFuncSetAttribute((const void*)mma_gemm<2, 256, 64, 2, 2>,
                         cudaFuncAttributeMaxDynamicSharedMemorySize, SM_AV);
    cudaFuncSetAttribute((const void*)mma_gemm<0, 128, 128, 3, 4>,
                         cudaFuncAttributeMaxDynamicSharedMemorySize, SM_OP);

    // 0+1. preamble: canon masks + transpose/round x,ctx + weight standardization
    preamble_kernel<<<2 + NB_TX + NB_TC + 4 * EDIM, 256>>>(
        x, ctx, mask_raw, mctx_raw, qw, kw, vw, ow,
        xr, cr, mask, mctx, wnq, wnkv, wno);

    // 2. merged Q + K + V projections: one launch, y-dispatch 8|8|8
    GP pQ = { xr, 1, (long)TLEN * EDIM, 0, EDIM,
              wnq, 1, 0, 0, EDIM,
              qbuf, 1, (long)TLEN * EDIM, 0, EDIM,
              EDIM, qb, 0, mask, 1, 1, TLEN, nullptr, 0, nullptr };
    GP pK = { cr, 1, (long)SLEN * CDIM, 0, CDIM,
              wnk, 1, 0, 0, CDIM,
              kbuf, 1, (long)SLEN * EDIM, 0, EDIM,
              CDIM, kb, 0, mctx, 1, 1, SLEN, nullptr, 0, nullptr };
    GP pV = { wnv, 1, 0, 0, CDIM,
              cr, 1, (long)SLEN * CDIM, 0, CDIM,
              vbuf, 1, (long)EDIM * SLEN, 0, SLEN,
              CDIM, vb, 1, mctx, 0, 1, SLEN, nullptr, 0, nullptr };
    mma_gemm<0, 128, 128, 3, 2><<<dim3(8, 24, BATCH), 128, SM_PROJ>>>(pQ, pK, pV, 8, 16);

    // 3. per-head LayerNorm over dh (q scaled by 1/256)
    ln_kernel<<<dim3(TLEN / 128, 3 * BATCH * NH), 128>>>(qbuf, kbuf, vbuf,
                                                         gq, bq, gk, bk, gv, bv);

    // 4. P[t,s] = mask[t] ? exp(sum_d q'[t,d] k[s,d]) : 0, + column partials -> rp
    GP pS = { qbuf, NH, (long)TLEN * EDIM, DH, EDIM,
              kbuf, NH, (long)SLEN * EDIM, DH, EDIM,
              pbuf, 1, (long)TLEN * SLEN, 0, SLEN,
              DH, nullptr, 0, mask, 1, NH, TLEN, nullptr, 0, rpbuf };
    mma_gemm<3, 128, 128, 2, 2><<<dim3(SLEN / 128, TLEN / 128, BATCH * NH), 128, SM_SC>>>(
        pS, pS, pS, 1 << 30, 1 << 30);

    // 5. finalize r; v' = v * r
    finalize_r<<<BATCH * NH * SLEN / 256, 256>>>(rpbuf, rbuf, mctx);
    vscale_kernel<<<BATCH * EDIM * SLEN / 4 / 256, 256>>>(vbuf, rbuf);

    // 6. att[t,d] = sum_s P[t,s] v'[d,s]  -> att [B][T][E] (head col slices)
    GP pA = { pbuf, 1, (long)TLEN * SLEN, 0, SLEN,
              vbuf, NH, (long)EDIM * SLEN, (long)DH * SLEN, SLEN,
              abuf, NH, (long)TLEN * EDIM, DH, EDIM,
              SLEN, nullptr, 0, mask, 1, 1, TLEN, nullptr, 0, nullptr };
    mma_gemm<2, 256, 64, 2, 2><<<dim3(1, TLEN / 256, BATCH * NH), 128, SM_AV>>>(
        pA, pA, pA, 1 << 30, 1 << 30);

    // 7. out[e,t] = sum_e' wno[e,e'] att[t,e'] + ob + mask + x
    GP pO = { wno, 1, 0, 0, EDIM,
              abuf, 1, (long)TLEN * EDIM, 0, EDIM,
              out, 1, (long)EDIM * TLEN, 0, TLEN,
              EDIM, ob, 1, mask, 0, 1, TLEN, x, (long)EDIM * TLEN, nullptr };
    mma_gemm<0, 128, 128, 3, 4><<<dim3(TLEN / 128, EDIM / 128, BATCH), 128, SM_OP>>>(
        pO, pO, pO, 1 << 30, 1 << 30);
}